// round 1
// baseline (speedup 1.0000x reference)
#include <cuda_runtime.h>

// Problem constants (fixed by setup_inputs)
#define N_NODES 100000
#define N_REL   3
#define N_EDGES 1600000
#define DIM     128                  // in/hidden width
#define OUT_DIM 64
#define K_DIM   (N_REL * DIM)        // 384 = GEMM K
#define RN      (N_REL * N_NODES)    // 300000 (relation,node) pairs
#define TOT_E   (N_REL * N_EDGES)    // 4800000 edges

// ---------------- scratch (device globals; no allocations allowed) ----------
__device__ int   g_deg_out[RN];
__device__ int   g_deg_in[RN];
__device__ float g_inv_out[RN];
__device__ float g_inv_in[RN];
__device__ int   g_row_start[RN];
__device__ int   g_cursor[RN];
__device__ int   g_bsum[1024];
__device__ int2  g_edges[TOT_E];            // {src, bits(inv_out[src])}
__device__ float g_hA[N_NODES * DIM];
__device__ float g_hB[N_NODES * DIM];
__device__ float g_P[N_NODES * K_DIM];      // [S1 h | S2 h | S3 h]

// ---------------- CSR build -------------------------------------------------
__global__ void k_zero_deg() {
    int i = blockIdx.x * blockDim.x + threadIdx.x;
    if (i < RN) { g_deg_out[i] = 0; g_deg_in[i] = 0; }
}

__global__ void k_count(const int* __restrict__ src, const int* __restrict__ dst) {
    int i = blockIdx.x * blockDim.x + threadIdx.x;
    if (i < TOT_E) {
        int r = i / N_EDGES;
        atomicAdd(&g_deg_out[r * N_NODES + src[i]], 1);
        atomicAdd(&g_deg_in [r * N_NODES + dst[i]], 1);
    }
}

__global__ void k_inv() {
    int i = blockIdx.x * blockDim.x + threadIdx.x;
    if (i < RN) {
        g_inv_out[i] = rsqrtf((float)max(g_deg_out[i], 1));
        g_inv_in [i] = rsqrtf((float)max(g_deg_in [i], 1));
    }
}

// exclusive scan of g_deg_in (300k elems) -> g_row_start, 3 passes
__global__ void k_scan1() {
    __shared__ int sh[1024];
    int t = threadIdx.x;
    int g = blockIdx.x * 1024 + t;
    int v = (g < RN) ? g_deg_in[g] : 0;
    sh[t] = v;
    __syncthreads();
    for (int off = 1; off < 1024; off <<= 1) {
        int x = (t >= off) ? sh[t - off] : 0;
        __syncthreads();
        sh[t] += x;
        __syncthreads();
    }
    if (g < RN) g_row_start[g] = sh[t] - v;       // exclusive
    if (t == 1023) g_bsum[blockIdx.x] = sh[t];    // block total
}

__global__ void k_scan2(int nblk) {
    __shared__ int sh[1024];
    int t = threadIdx.x;
    int v = (t < nblk) ? g_bsum[t] : 0;
    sh[t] = v;
    __syncthreads();
    for (int off = 1; off < 1024; off <<= 1) {
        int x = (t >= off) ? sh[t - off] : 0;
        __syncthreads();
        sh[t] += x;
        __syncthreads();
    }
    if (t < nblk) g_bsum[t] = sh[t] - v;          // exclusive
}

__global__ void k_scan3() {
    int i = blockIdx.x * blockDim.x + threadIdx.x;
    if (i < RN) {
        int rs = g_row_start[i] + g_bsum[i >> 10];
        g_row_start[i] = rs;
        g_cursor[i]    = rs;
    }
}

__global__ void k_fill(const int* __restrict__ src, const int* __restrict__ dst) {
    int i = blockIdx.x * blockDim.x + threadIdx.x;
    if (i < TOT_E) {
        int r = i / N_EDGES;
        int s = src[i];
        int d = dst[i];
        int pos = atomicAdd(&g_cursor[r * N_NODES + d], 1);
        g_edges[pos] = make_int2(s, __float_as_int(g_inv_out[r * N_NODES + s]));
    }
}

// ---------------- aggregation: P[n, r*128..] = inv_in * sum_e w_e * h[src_e] ---
// one warp per (relation, node); each lane owns one float4 (4 cols of 128)
__global__ void k_agg(const float4* hx, int sel) {
    const float4* h = (sel == 0) ? hx
                    : (sel == 1) ? (const float4*)g_hA
                                 : (const float4*)g_hB;
    int wid  = (blockIdx.x * blockDim.x + threadIdx.x) >> 5;
    int lane = threadIdx.x & 31;
    if (wid >= RN) return;
    int start = g_row_start[wid];
    int len   = g_deg_in[wid];
    float4 acc = make_float4(0.f, 0.f, 0.f, 0.f);
    for (int base = 0; base < len; base += 32) {
        int rem = len - base;
        int2 e = (lane < rem) ? g_edges[start + base + lane] : make_int2(0, 0);
        int cnt = min(32, rem);
        for (int k = 0; k < cnt; k++) {
            int   s = __shfl_sync(0xffffffffu, e.x, k);
            float w = __int_as_float(__shfl_sync(0xffffffffu, e.y, k));
            float4 v = h[s * 32 + lane];
            acc.x = fmaf(w, v.x, acc.x);
            acc.y = fmaf(w, v.y, acc.y);
            acc.z = fmaf(w, v.z, acc.z);
            acc.w = fmaf(w, v.w, acc.w);
        }
    }
    float si = g_inv_in[wid];
    acc.x *= si; acc.y *= si; acc.z *= si; acc.w *= si;
    int n = wid % N_NODES;
    int r = wid / N_NODES;
    ((float4*)g_P)[n * (K_DIM / 4) + r * 32 + lane] = acc;
}

// ---------------- GEMM: C = [relu]( P @ W + sum_r b_r ) ---------------------
// P: [N_NODES x 384], W: [384 x ncols] (== the raw (R,128,do) tensor), b: [3 x ncols]
// 128x128 tile, BK=8, 256 threads, 8x8 per thread
template <bool RELU>
__global__ void __launch_bounds__(256) k_gemm(const float* __restrict__ W,
                                              const float* __restrict__ bias,
                                              float* Cext, int osel, int ncols) {
    float* C = (osel == 0) ? Cext : (osel == 1) ? g_hA : g_hB;
    const float* A = g_P;

    __shared__ float As[8][128];
    __shared__ float Bs[8][128];

    int t    = threadIdx.x;
    int row0 = blockIdx.x * 128;

    int a_row = t >> 1;                 // 0..127
    int a_k4  = (t & 1) * 4;            // 0 or 4
    int b_kk  = t >> 5;                 // 0..7
    int b_col = (t & 31) * 4;           // 0..124
    int ty    = t >> 4;                 // 0..15
    int tx    = t & 15;                 // 0..15

    float acc[8][8];
#pragma unroll
    for (int i = 0; i < 8; i++)
#pragma unroll
        for (int j = 0; j < 8; j++) acc[i][j] = 0.f;

    for (int k0 = 0; k0 < K_DIM; k0 += 8) {
        int ar = row0 + a_row;
        float4 av = make_float4(0.f, 0.f, 0.f, 0.f);
        if (ar < N_NODES)
            av = *(const float4*)&A[ar * K_DIM + k0 + a_k4];
        float4 bv = make_float4(0.f, 0.f, 0.f, 0.f);
        if (b_col < ncols)
            bv = *(const float4*)&W[(k0 + b_kk) * ncols + b_col];
        __syncthreads();
        As[a_k4 + 0][a_row] = av.x;
        As[a_k4 + 1][a_row] = av.y;
        As[a_k4 + 2][a_row] = av.z;
        As[a_k4 + 3][a_row] = av.w;
        *(float4*)&Bs[b_kk][b_col] = bv;
        __syncthreads();
#pragma unroll
        for (int kk = 0; kk < 8; kk++) {
            float a_[8], b_[8];
#pragma unroll
            for (int i = 0; i < 8; i++) a_[i] = As[kk][ty * 8 + i];
#pragma unroll
            for (int j = 0; j < 8; j++) b_[j] = Bs[kk][tx * 8 + j];
#pragma unroll
            for (int i = 0; i < 8; i++)
#pragma unroll
                for (int j = 0; j < 8; j++)
                    acc[i][j] = fmaf(a_[i], b_[j], acc[i][j]);
        }
    }

#pragma unroll
    for (int i = 0; i < 8; i++) {
        int row = row0 + ty * 8 + i;
        if (row >= N_NODES) continue;
#pragma unroll
        for (int j = 0; j < 8; j++) {
            int col = tx * 8 + j;
            if (col >= ncols) continue;
            float v = acc[i][j] + bias[col] + bias[ncols + col] + bias[2 * ncols + col];
            if (RELU) v = fmaxf(v, 0.f);
            C[row * ncols + col] = v;
        }
    }
}

// ---------------- launch ----------------------------------------------------
extern "C" void kernel_launch(void* const* d_in, const int* in_sizes, int n_in,
                              void* d_out, int out_size) {
    const float* x   = (const float*)d_in[0];
    const int*   src = (const int*)d_in[1];
    const int*   dst = (const int*)d_in[2];
    const float* W[6];
    const float* b[6];
    for (int l = 0; l < 6; l++) {
        W[l] = (const float*)d_in[3 + 2 * l];
        b[l] = (const float*)d_in[4 + 2 * l];
    }

    const int T = 256;
    // degree norms + CSR build (recomputed every call; deterministic work)
    k_zero_deg<<<(RN + T - 1) / T, T>>>();
    k_count<<<(TOT_E + T - 1) / T, T>>>(src, dst);
    k_inv<<<(RN + T - 1) / T, T>>>();
    int nblk = (RN + 1023) / 1024;
    k_scan1<<<nblk, 1024>>>();
    k_scan2<<<1, 1024>>>(nblk);
    k_scan3<<<(RN + T - 1) / T, T>>>();
    k_fill<<<(TOT_E + T - 1) / T, T>>>(src, dst);

    int agg_blocks  = (RN * 32 + T - 1) / T;
    int gemm_blocks = (N_NODES + 127) / 128;

    // layer schedule: in-sel (0=x,1=hA,2=hB), out-sel (0=d_out,1=hA,2=hB)
    int in_sel [6] = {0, 1, 2, 1, 2, 1};
    int out_sel[6] = {1, 2, 1, 2, 1, 0};

    for (int l = 0; l < 6; l++) {
        k_agg<<<agg_blocks, T>>>((const float4*)x, in_sel[l]);
        int ncols = (l == 5) ? OUT_DIM : DIM;
        if (l == 5)
            k_gemm<false><<<gemm_blocks, T>>>(W[l], b[l], (float*)d_out, 0, ncols);
        else
            k_gemm<true><<<gemm_blocks, T>>>(W[l], b[l], nullptr, out_sel[l], ncols);
    }
}

// round 2
// speedup vs baseline: 1.0081x; 1.0081x over previous
#include <cuda_runtime.h>

// Problem constants (fixed by setup_inputs)
#define N_NODES 100000
#define N_REL   3
#define N_EDGES 1600000
#define DIM     128                  // in/hidden width
#define OUT_DIM 64
#define K_DIM   (N_REL * DIM)        // 384 = GEMM K
#define RN      (N_REL * N_NODES)    // 300000 (relation,node) pairs
#define TOT_E   (N_REL * N_EDGES)    // 4800000 edges

// ---------------- scratch (device globals; no allocations allowed) ----------
__device__ int   g_deg_out[RN];
__device__ int   g_deg_in[RN];
__device__ float g_inv_out[RN];
__device__ float g_inv_in[RN];
__device__ int   g_row_start[RN];
__device__ int   g_cursor[RN];
__device__ int   g_bsum[1024];
__device__ int2  g_edges[TOT_E];            // {src, bits(inv_out[src])}
__device__ float g_hA[N_NODES * DIM];
__device__ float g_hB[N_NODES * DIM];
__device__ float g_P[N_NODES * K_DIM];      // [S1 h | S2 h | S3 h]

// ---------------- CSR build -------------------------------------------------
__global__ void k_zero_deg() {
    int i = blockIdx.x * blockDim.x + threadIdx.x;
    if (i < RN) { g_deg_out[i] = 0; g_deg_in[i] = 0; }
}

__global__ void k_count(const int* __restrict__ src, const int* __restrict__ dst) {
    int i = blockIdx.x * blockDim.x + threadIdx.x;
    if (i < TOT_E) {
        int r = i / N_EDGES;
        atomicAdd(&g_deg_out[r * N_NODES + src[i]], 1);
        atomicAdd(&g_deg_in [r * N_NODES + dst[i]], 1);
    }
}

__global__ void k_inv() {
    int i = blockIdx.x * blockDim.x + threadIdx.x;
    if (i < RN) {
        g_inv_out[i] = rsqrtf((float)max(g_deg_out[i], 1));
        g_inv_in [i] = rsqrtf((float)max(g_deg_in [i], 1));
    }
}

// exclusive scan of g_deg_in (300k elems) -> g_row_start, 3 passes
__global__ void k_scan1() {
    __shared__ int sh[1024];
    int t = threadIdx.x;
    int g = blockIdx.x * 1024 + t;
    int v = (g < RN) ? g_deg_in[g] : 0;
    sh[t] = v;
    __syncthreads();
    for (int off = 1; off < 1024; off <<= 1) {
        int x = (t >= off) ? sh[t - off] : 0;
        __syncthreads();
        sh[t] += x;
        __syncthreads();
    }
    if (g < RN) g_row_start[g] = sh[t] - v;       // exclusive
    if (t == 1023) g_bsum[blockIdx.x] = sh[t];    // block total
}

__global__ void k_scan2(int nblk) {
    __shared__ int sh[1024];
    int t = threadIdx.x;
    int v = (t < nblk) ? g_bsum[t] : 0;
    sh[t] = v;
    __syncthreads();
    for (int off = 1; off < 1024; off <<= 1) {
        int x = (t >= off) ? sh[t - off] : 0;
        __syncthreads();
        sh[t] += x;
        __syncthreads();
    }
    if (t < nblk) g_bsum[t] = sh[t] - v;          // exclusive
}

__global__ void k_scan3() {
    int i = blockIdx.x * blockDim.x + threadIdx.x;
    if (i < RN) {
        int rs = g_row_start[i] + g_bsum[i >> 10];
        g_row_start[i] = rs;
        g_cursor[i]    = rs;
    }
}

__global__ void k_fill(const int* __restrict__ src, const int* __restrict__ dst) {
    int i = blockIdx.x * blockDim.x + threadIdx.x;
    if (i < TOT_E) {
        int r = i / N_EDGES;
        int s = src[i];
        int d = dst[i];
        int pos = atomicAdd(&g_cursor[r * N_NODES + d], 1);
        g_edges[pos] = make_int2(s, __float_as_int(g_inv_out[r * N_NODES + s]));
    }
}

// ---------------- aggregation: P[n, r*128..] = inv_in * sum_e w_e * h[src_e] ---
// one warp per (relation, node); each lane owns one float4 (4 cols of 128)
__global__ void k_agg(const float4* hx, int sel) {
    const float4* h = (sel == 0) ? hx
                    : (sel == 1) ? (const float4*)g_hA
                                 : (const float4*)g_hB;
    int wid  = (blockIdx.x * blockDim.x + threadIdx.x) >> 5;
    int lane = threadIdx.x & 31;
    if (wid >= RN) return;
    int start = g_row_start[wid];
    int len   = g_deg_in[wid];
    float4 acc = make_float4(0.f, 0.f, 0.f, 0.f);
    for (int base = 0; base < len; base += 32) {
        int rem = len - base;
        int2 e = (lane < rem) ? g_edges[start + base + lane] : make_int2(0, 0);
        int cnt = min(32, rem);
        for (int k = 0; k < cnt; k++) {
            int   s = __shfl_sync(0xffffffffu, e.x, k);
            float w = __int_as_float(__shfl_sync(0xffffffffu, e.y, k));
            float4 v = h[s * 32 + lane];
            acc.x = fmaf(w, v.x, acc.x);
            acc.y = fmaf(w, v.y, acc.y);
            acc.z = fmaf(w, v.z, acc.z);
            acc.w = fmaf(w, v.w, acc.w);
        }
    }
    float si = g_inv_in[wid];
    acc.x *= si; acc.y *= si; acc.z *= si; acc.w *= si;
    int n = wid % N_NODES;
    int r = wid / N_NODES;
    ((float4*)g_P)[n * (K_DIM / 4) + r * 32 + lane] = acc;
}

// ---------------- GEMM: C = [relu]( P @ W + sum_r b_r ) ---------------------
// P: [N_NODES x 384], W: [384 x ncols] (== the raw (R,128,do) tensor), b: [3 x ncols]
// 128x128 tile, BK=8, 256 threads, 8x8 per thread
template <bool RELU>
__global__ void __launch_bounds__(256) k_gemm(const float* __restrict__ W,
                                              const float* __restrict__ bias,
                                              float* Cext, int osel, int ncols) {
    float* C = (osel == 0) ? Cext : (osel == 1) ? g_hA : g_hB;
    const float* A = g_P;

    __shared__ float As[8][128];
    __shared__ float Bs[8][128];

    int t    = threadIdx.x;
    int row0 = blockIdx.x * 128;

    int a_row = t >> 1;                 // 0..127
    int a_k4  = (t & 1) * 4;            // 0 or 4
    int b_kk  = t >> 5;                 // 0..7
    int b_col = (t & 31) * 4;           // 0..124
    int ty    = t >> 4;                 // 0..15
    int tx    = t & 15;                 // 0..15

    float acc[8][8];
#pragma unroll
    for (int i = 0; i < 8; i++)
#pragma unroll
        for (int j = 0; j < 8; j++) acc[i][j] = 0.f;

    for (int k0 = 0; k0 < K_DIM; k0 += 8) {
        int ar = row0 + a_row;
        float4 av = make_float4(0.f, 0.f, 0.f, 0.f);
        if (ar < N_NODES)
            av = *(const float4*)&A[ar * K_DIM + k0 + a_k4];
        float4 bv = make_float4(0.f, 0.f, 0.f, 0.f);
        if (b_col < ncols)
            bv = *(const float4*)&W[(k0 + b_kk) * ncols + b_col];
        __syncthreads();
        As[a_k4 + 0][a_row] = av.x;
        As[a_k4 + 1][a_row] = av.y;
        As[a_k4 + 2][a_row] = av.z;
        As[a_k4 + 3][a_row] = av.w;
        *(float4*)&Bs[b_kk][b_col] = bv;
        __syncthreads();
#pragma unroll
        for (int kk = 0; kk < 8; kk++) {
            float a_[8], b_[8];
#pragma unroll
            for (int i = 0; i < 8; i++) a_[i] = As[kk][ty * 8 + i];
#pragma unroll
            for (int j = 0; j < 8; j++) b_[j] = Bs[kk][tx * 8 + j];
#pragma unroll
            for (int i = 0; i < 8; i++)
#pragma unroll
                for (int j = 0; j < 8; j++)
                    acc[i][j] = fmaf(a_[i], b_[j], acc[i][j]);
        }
    }

#pragma unroll
    for (int i = 0; i < 8; i++) {
        int row = row0 + ty * 8 + i;
        if (row >= N_NODES) continue;
#pragma unroll
        for (int j = 0; j < 8; j++) {
            int col = tx * 8 + j;
            if (col >= ncols) continue;
            float v = acc[i][j] + bias[col] + bias[ncols + col] + bias[2 * ncols + col];
            if (RELU) v = fmaxf(v, 0.f);
            C[row * ncols + col] = v;
        }
    }
}

// ---------------- launch ----------------------------------------------------
extern "C" void kernel_launch(void* const* d_in, const int* in_sizes, int n_in,
                              void* d_out, int out_size) {
    const float* x   = (const float*)d_in[0];
    const int*   src = (const int*)d_in[1];
    const int*   dst = (const int*)d_in[2];
    const float* W[6];
    const float* b[6];
    for (int l = 0; l < 6; l++) {
        W[l] = (const float*)d_in[3 + 2 * l];
        b[l] = (const float*)d_in[4 + 2 * l];
    }

    const int T = 256;
    // degree norms + CSR build (recomputed every call; deterministic work)
    k_zero_deg<<<(RN + T - 1) / T, T>>>();
    k_count<<<(TOT_E + T - 1) / T, T>>>(src, dst);
    k_inv<<<(RN + T - 1) / T, T>>>();
    int nblk = (RN + 1023) / 1024;
    k_scan1<<<nblk, 1024>>>();
    k_scan2<<<1, 1024>>>(nblk);
    k_scan3<<<(RN + T - 1) / T, T>>>();
    k_fill<<<(TOT_E + T - 1) / T, T>>>(src, dst);

    int agg_blocks  = (RN * 32 + T - 1) / T;
    int gemm_blocks = (N_NODES + 127) / 128;

    // layer schedule: in-sel (0=x,1=hA,2=hB), out-sel (0=d_out,1=hA,2=hB)
    int in_sel [6] = {0, 1, 2, 1, 2, 1};
    int out_sel[6] = {1, 2, 1, 2, 1, 0};

    for (int l = 0; l < 6; l++) {
        k_agg<<<agg_blocks, T>>>((const float4*)x, in_sel[l]);
        int ncols = (l == 5) ? OUT_DIM : DIM;
        if (l == 5)
            k_gemm<false><<<gemm_blocks, T>>>(W[l], b[l], (float*)d_out, 0, ncols);
        else
            k_gemm<true><<<gemm_blocks, T>>>(W[l], b[l], nullptr, out_sel[l], ncols);
    }
}

// round 4
// speedup vs baseline: 1.4051x; 1.3939x over previous
#include <cuda_runtime.h>
#include <cuda_bf16.h>
#include <cstdint>

// Problem constants (fixed by setup_inputs)
#define N_NODES 100000
#define NPAD    100096               // 782 * 128 (padded M for GEMM tiles)
#define N_REL   3
#define N_EDGES 1600000
#define DIM     128
#define OUT_DIM 64
#define K_DIM   (N_REL * DIM)        // 384
#define RN      (N_REL * N_NODES)    // 300000
#define TOT_E   (N_REL * N_EDGES)    // 4800000

// ---------------- scratch (device globals; zero-initialized) ----------------
__device__ int   g_deg_out[RN];
__device__ int   g_deg_in[RN];
__device__ float g_inv_out[RN];
__device__ float g_inv_in[RN];
__device__ int   g_row_start[RN];
__device__ int   g_cursor[RN];
__device__ int   g_bsum_scan[1024];
__device__ int2  g_edges[TOT_E];             // {src, bits(inv_out[src])}
__device__ float g_hA[N_NODES * DIM];
__device__ float g_hB[N_NODES * DIM];
__device__ __nv_bfloat16 g_Ph[NPAD * K_DIM]; // split-hi of aggregated features
__device__ __nv_bfloat16 g_Pl[NPAD * K_DIM]; // split-lo
__device__ __nv_bfloat16 g_Wh[K_DIM * 128];  // W hi  [384][128] (cols zero-padded)
__device__ __nv_bfloat16 g_Wl[K_DIM * 128];  // W lo
__device__ float g_bias[128];                // sum_r b_r, padded

__device__ __forceinline__ uint32_t smem_u32(const void* p) {
    uint32_t a;
    asm("{ .reg .u64 t; cvta.to.shared.u64 t, %1; cvt.u32.u64 %0, t; }" : "=r"(a) : "l"(p));
    return a;
}

// ---------------- CSR build -------------------------------------------------
__global__ void k_zero_deg() {
    int i = blockIdx.x * blockDim.x + threadIdx.x;
    if (i < RN) { g_deg_out[i] = 0; g_deg_in[i] = 0; }
}
__global__ void k_count(const int* __restrict__ src, const int* __restrict__ dst) {
    int i = blockIdx.x * blockDim.x + threadIdx.x;
    if (i < TOT_E) {
        int r = i / N_EDGES;
        atomicAdd(&g_deg_out[r * N_NODES + src[i]], 1);
        atomicAdd(&g_deg_in [r * N_NODES + dst[i]], 1);
    }
}
__global__ void k_inv() {
    int i = blockIdx.x * blockDim.x + threadIdx.x;
    if (i < RN) {
        g_inv_out[i] = rsqrtf((float)max(g_deg_out[i], 1));
        g_inv_in [i] = rsqrtf((float)max(g_deg_in [i], 1));
    }
}
__global__ void k_scan1() {
    __shared__ int sh[1024];
    int t = threadIdx.x, g = blockIdx.x * 1024 + t;
    int v = (g < RN) ? g_deg_in[g] : 0;
    sh[t] = v; __syncthreads();
    for (int off = 1; off < 1024; off <<= 1) {
        int x = (t >= off) ? sh[t - off] : 0;
        __syncthreads(); sh[t] += x; __syncthreads();
    }
    if (g < RN) g_row_start[g] = sh[t] - v;
    if (t == 1023) g_bsum_scan[blockIdx.x] = sh[t];
}
__global__ void k_scan2(int nblk) {
    __shared__ int sh[1024];
    int t = threadIdx.x;
    int v = (t < nblk) ? g_bsum_scan[t] : 0;
    sh[t] = v; __syncthreads();
    for (int off = 1; off < 1024; off <<= 1) {
        int x = (t >= off) ? sh[t - off] : 0;
        __syncthreads(); sh[t] += x; __syncthreads();
    }
    if (t < nblk) g_bsum_scan[t] = sh[t] - v;
}
__global__ void k_scan3() {
    int i = blockIdx.x * blockDim.x + threadIdx.x;
    if (i < RN) {
        int rs = g_row_start[i] + g_bsum_scan[i >> 10];
        g_row_start[i] = rs;
        g_cursor[i]    = rs;
    }
}
__global__ void k_fill(const int* __restrict__ src, const int* __restrict__ dst) {
    int i = blockIdx.x * blockDim.x + threadIdx.x;
    if (i < TOT_E) {
        int r = i / N_EDGES;
        int s = src[i], d = dst[i];
        int pos = atomicAdd(&g_cursor[r * N_NODES + d], 1);
        g_edges[pos] = make_int2(s, __float_as_int(g_inv_out[r * N_NODES + s]));
    }
}

// ---------------- aggregation -> split-bf16 P -------------------------------
// one warp per (relation, node); each lane owns 4 cols of 128
__global__ void k_agg(const float4* hx, int sel) {
    const float4* h = (sel == 0) ? hx
                    : (sel == 1) ? (const float4*)g_hA
                                 : (const float4*)g_hB;
    int wid  = (blockIdx.x * blockDim.x + threadIdx.x) >> 5;
    int lane = threadIdx.x & 31;
    if (wid >= RN) return;
    int start = g_row_start[wid];
    int len   = g_deg_in[wid];
    float4 acc = make_float4(0.f, 0.f, 0.f, 0.f);
    for (int base = 0; base < len; base += 32) {
        int rem = len - base;
        int2 e = (lane < rem) ? g_edges[start + base + lane] : make_int2(0, 0);
        int cnt = min(32, rem);
        for (int k = 0; k < cnt; k++) {
            int   s = __shfl_sync(0xffffffffu, e.x, k);
            float w = __int_as_float(__shfl_sync(0xffffffffu, e.y, k));
            float4 v = h[s * 32 + lane];
            acc.x = fmaf(w, v.x, acc.x);
            acc.y = fmaf(w, v.y, acc.y);
            acc.z = fmaf(w, v.z, acc.z);
            acc.w = fmaf(w, v.w, acc.w);
        }
    }
    float si = g_inv_in[wid];
    acc.x *= si; acc.y *= si; acc.z *= si; acc.w *= si;
    int n = wid % N_NODES;
    int r = wid / N_NODES;
    __nv_bfloat16 hx0 = __float2bfloat16_rn(acc.x);
    __nv_bfloat16 hx1 = __float2bfloat16_rn(acc.y);
    __nv_bfloat16 hx2 = __float2bfloat16_rn(acc.z);
    __nv_bfloat16 hx3 = __float2bfloat16_rn(acc.w);
    __nv_bfloat16 lx0 = __float2bfloat16_rn(acc.x - __bfloat162float(hx0));
    __nv_bfloat16 lx1 = __float2bfloat16_rn(acc.y - __bfloat162float(hx1));
    __nv_bfloat16 lx2 = __float2bfloat16_rn(acc.z - __bfloat162float(hx2));
    __nv_bfloat16 lx3 = __float2bfloat16_rn(acc.w - __bfloat162float(hx3));
    uint2 hi, lo;
    hi.x = (uint32_t)__bfloat16_as_ushort(hx1) << 16 | __bfloat16_as_ushort(hx0);
    hi.y = (uint32_t)__bfloat16_as_ushort(hx3) << 16 | __bfloat16_as_ushort(hx2);
    lo.x = (uint32_t)__bfloat16_as_ushort(lx1) << 16 | __bfloat16_as_ushort(lx0);
    lo.y = (uint32_t)__bfloat16_as_ushort(lx3) << 16 | __bfloat16_as_ushort(lx2);
    int idx8 = n * 96 + r * 32 + lane;         // uint2 index into [NPAD][384]
    ((uint2*)g_Ph)[idx8] = hi;
    ((uint2*)g_Pl)[idx8] = lo;
}

// ---------------- per-layer weight prep: bf16 split + combined bias ---------
// W is (R, di, do) row-major == [384][ncols]; pad cols to 128.
__global__ void k_prep(const float* __restrict__ W, const float* __restrict__ b, int ncols) {
    int idx = blockIdx.x * blockDim.x + threadIdx.x;   // idx = k*128 + n
    if (idx < K_DIM * 128) {
        int k = idx >> 7;
        int n = idx & 127;
        float w = (n < ncols) ? W[k * ncols + n] : 0.f;
        __nv_bfloat16 hi = __float2bfloat16_rn(w);
        g_Wh[idx] = hi;
        g_Wl[idx] = __float2bfloat16_rn(w - __bfloat162float(hi));
    }
    if (idx < 128)
        g_bias[idx] = (idx < ncols) ? b[idx] + b[ncols + idx] + b[2 * ncols + idx] : 0.f;
}

// ---------------- HMMA GEMM: C = [relu]( P @ W + bsum ) ---------------------
// 128x128 CTA tile, 8 warps of 32x64, mma.m16n8k16 bf16, 3-pass split-fp32.
#define ASTRIDE 40    // 32 + 8 pad (bf16)
#define BSTRIDE 136   // 128 + 8 pad (bf16)
template <bool RELU>
__global__ void __launch_bounds__(256) k_gemm_mma(float* Cext, int osel, int ncols) {
    __shared__ __align__(16) __nv_bfloat16 As[128 * ASTRIDE];
    __shared__ __align__(16) __nv_bfloat16 Bs[32 * BSTRIDE];

    int t = threadIdx.x;
    int w = t >> 5, lane = t & 31;
    int wm = w & 3, wn = w >> 2;
    int row0 = blockIdx.x * 128;

    float d[2][8][4];
#pragma unroll
    for (int i = 0; i < 2; i++)
#pragma unroll
        for (int j = 0; j < 8; j++)
#pragma unroll
            for (int k = 0; k < 4; k++) d[i][j][k] = 0.f;

    int a_row = t >> 1;           // 0..127
    int a_col = (t & 1) * 16;     // 0 or 16
    int b_row = t >> 3;           // 0..31
    int b_col = (t & 7) * 16;     // 0..112

    uint32_t sA = smem_u32(As), sB = smem_u32(Bs);

    uint4 ra0, ra1, rb0, rb1;
    {
        const __nv_bfloat16* ap = g_Ph + (size_t)(row0 + a_row) * K_DIM + a_col;
        ra0 = *(const uint4*)ap; ra1 = *(const uint4*)(ap + 8);
        const __nv_bfloat16* bp = g_Wh + b_row * 128 + b_col;
        rb0 = *(const uint4*)bp; rb1 = *(const uint4*)(bp + 8);
    }

    const int NIT = 36;   // 3 passes x 12 chunks of BK=32
    for (int it = 0; it < NIT; it++) {
        *(uint4*)&As[a_row * ASTRIDE + a_col]     = ra0;
        *(uint4*)&As[a_row * ASTRIDE + a_col + 8] = ra1;
        *(uint4*)&Bs[b_row * BSTRIDE + b_col]     = rb0;
        *(uint4*)&Bs[b_row * BSTRIDE + b_col + 8] = rb1;
        __syncthreads();

        if (it + 1 < NIT) {
            int nx = it + 1;
            int p  = nx / 12;
            int kk = (nx - p * 12) * 32;
            const __nv_bfloat16* Ab = (p == 1) ? g_Pl : g_Ph;
            const __nv_bfloat16* Bb = (p == 2) ? g_Wl : g_Wh;
            const __nv_bfloat16* ap = Ab + (size_t)(row0 + a_row) * K_DIM + kk + a_col;
            ra0 = *(const uint4*)ap; ra1 = *(const uint4*)(ap + 8);
            const __nv_bfloat16* bp = Bb + (size_t)(kk + b_row) * 128 + b_col;
            rb0 = *(const uint4*)bp; rb1 = *(const uint4*)(bp + 8);
        }

#pragma unroll
        for (int kh = 0; kh < 32; kh += 16) {
            uint32_t a[2][4];
#pragma unroll
            for (int mi = 0; mi < 2; mi++) {
                uint32_t addr = sA + (uint32_t)(((wm * 32 + mi * 16 + (lane & 15)) * ASTRIDE
                                                 + kh + (lane >> 4) * 8) * 2);
                asm volatile("ldmatrix.sync.aligned.m8n8.x4.shared.b16 {%0,%1,%2,%3}, [%4];"
                    : "=r"(a[mi][0]), "=r"(a[mi][1]), "=r"(a[mi][2]), "=r"(a[mi][3]) : "r"(addr));
            }
            uint32_t bfr[8][2];
#pragma unroll
            for (int nj = 0; nj < 4; nj++) {
                uint32_t addr = sB + (uint32_t)(((kh + (lane & 15)) * BSTRIDE
                                                 + wn * 64 + nj * 16 + (lane >> 4) * 8) * 2);
                uint32_t b0, b1, b2, b3;
                asm volatile("ldmatrix.sync.aligned.m8n8.x4.trans.shared.b16 {%0,%1,%2,%3}, [%4];"
                    : "=r"(b0), "=r"(b1), "=r"(b2), "=r"(b3) : "r"(addr));
                bfr[nj * 2][0] = b0; bfr[nj * 2][1] = b1;
                bfr[nj * 2 + 1][0] = b2; bfr[nj * 2 + 1][1] = b3;
            }
#pragma unroll
            for (int mi = 0; mi < 2; mi++)
#pragma unroll
                for (int nj = 0; nj < 8; nj++)
                    asm volatile("mma.sync.aligned.m16n8k16.row.col.f32.bf16.bf16.f32 "
                        "{%0,%1,%2,%3}, {%4,%5,%6,%7}, {%8,%9}, {%0,%1,%2,%3};"
                        : "+f"(d[mi][nj][0]), "+f"(d[mi][nj][1]),
                          "+f"(d[mi][nj][2]), "+f"(d[mi][nj][3])
                        : "r"(a[mi][0]), "r"(a[mi][1]), "r"(a[mi][2]), "r"(a[mi][3]),
                          "r"(bfr[nj][0]), "r"(bfr[nj][1]));
        }
        __syncthreads();
    }

    // epilogue
    if (wn * 64 >= ncols) return;
    float* out = (osel == 0) ? Cext : (osel == 1) ? g_hA : g_hB;
    int cbase = wn * 64 + (lane & 3) * 2;
#pragma unroll
    for (int mi = 0; mi < 2; mi++) {
#pragma unroll
        for (int half = 0; half < 2; half++) {
            int row = row0 + wm * 32 + mi * 16 + (lane >> 2) + half * 8;
            if (row >= N_NODES) continue;
            float* dst = out + (size_t)row * ncols;
#pragma unroll
            for (int nj = 0; nj < 8; nj++) {
                int c = cbase + nj * 8;
                float v0 = d[mi][nj][half * 2 + 0] + g_bias[c];
                float v1 = d[mi][nj][half * 2 + 1] + g_bias[c + 1];
                if (RELU) { v0 = fmaxf(v0, 0.f); v1 = fmaxf(v1, 0.f); }
                *(float2*)(dst + c) = make_float2(v0, v1);
            }
        }
    }
}

// ---------------- launch ----------------------------------------------------
extern "C" void kernel_launch(void* const* d_in, const int* in_sizes, int n_in,
                              void* d_out, int out_size) {
    const float* x   = (const float*)d_in[0];
    const int*   src = (const int*)d_in[1];
    const int*   dst = (const int*)d_in[2];
    const float* W[6];
    const float* b[6];
    for (int l = 0; l < 6; l++) {
        W[l] = (const float*)d_in[3 + 2 * l];
        b[l] = (const float*)d_in[4 + 2 * l];
    }

    const int T = 256;
    k_zero_deg<<<(RN + T - 1) / T, T>>>();
    k_count<<<(TOT_E + T - 1) / T, T>>>(src, dst);
    k_inv<<<(RN + T - 1) / T, T>>>();
    int nblk = (RN + 1023) / 1024;
    k_scan1<<<nblk, 1024>>>();
    k_scan2<<<1, 1024>>>(nblk);
    k_scan3<<<(RN + T - 1) / T, T>>>();
    k_fill<<<(TOT_E + T - 1) / T, T>>>(src, dst);

    int agg_blocks  = (RN * 32 + T - 1) / T;
    int gemm_blocks = NPAD / 128;   // 782

    int in_sel [6] = {0, 1, 2, 1, 2, 1};
    int out_sel[6] = {1, 2, 1, 2, 1, 0};

    for (int l = 0; l < 6; l++) {
        int ncols = (l == 5) ? OUT_DIM : DIM;
        k_prep<<<(K_DIM * 128 + T - 1) / T, T>>>(W[l], b[l], ncols);
        k_agg<<<agg_blocks, T>>>((const float4*)x, in_sel[l]);
        if (l == 5)
            k_gemm_mma<false><<<gemm_blocks, T>>>((float*)d_out, 0, ncols);
        else
            k_gemm_mma<true><<<gemm_blocks, T>>>(nullptr, out_sel[l], ncols);
    }
}

// round 5
// speedup vs baseline: 1.6041x; 1.1416x over previous
#include <cuda_runtime.h>
#include <cuda_bf16.h>
#include <cuda_fp16.h>
#include <cstdint>

// Problem constants (fixed by setup_inputs)
#define N_NODES 100000
#define NPAD    100096               // 782 * 128 (padded M for GEMM tiles)
#define N_REL   3
#define N_EDGES 1600000
#define DIM     128
#define OUT_DIM 64
#define K_DIM   (N_REL * DIM)        // 384
#define RN      (N_REL * N_NODES)    // 300000
#define TOT_E   (N_REL * N_EDGES)    // 4800000

// ---------------- scratch (device globals; zero-initialized) ----------------
__device__ int   g_deg_out[RN];
__device__ int   g_deg_in[RN];
__device__ float g_inv_out[RN];
__device__ float g_inv_in[RN];
__device__ int   g_row_start[RN];
__device__ int   g_cursor[RN];
__device__ int   g_bsum_scan[1024];
__device__ int2  g_edges[TOT_E];             // {src, bits(inv_out[src])}
__device__ __align__(16) __half g_x16[N_NODES * DIM];   // fp16 input features
__device__ __align__(16) __half g_h16A[N_NODES * DIM];  // fp16 hidden A
__device__ __align__(16) __half g_h16B[N_NODES * DIM];  // fp16 hidden B
__device__ __nv_bfloat16 g_Ph[NPAD * K_DIM]; // split-hi of aggregated features
__device__ __nv_bfloat16 g_Pl[NPAD * K_DIM]; // split-lo
__device__ __nv_bfloat16 g_Wh[K_DIM * 128];  // W hi  [384][128] (cols zero-padded)
__device__ __nv_bfloat16 g_Wl[K_DIM * 128];  // W lo
__device__ float g_bias[128];                // sum_r b_r, padded

__device__ __forceinline__ uint32_t smem_u32(const void* p) {
    uint32_t a;
    asm("{ .reg .u64 t; cvta.to.shared.u64 t, %1; cvt.u32.u64 %0, t; }" : "=r"(a) : "l"(p));
    return a;
}

// ---------------- CSR build -------------------------------------------------
__global__ void k_zero_deg() {
    int i = blockIdx.x * blockDim.x + threadIdx.x;
    if (i < RN) { g_deg_out[i] = 0; g_deg_in[i] = 0; }
}
__global__ void k_count(const int* __restrict__ src, const int* __restrict__ dst) {
    int i = blockIdx.x * blockDim.x + threadIdx.x;
    if (i < TOT_E) {
        int r = i / N_EDGES;
        atomicAdd(&g_deg_out[r * N_NODES + src[i]], 1);
        atomicAdd(&g_deg_in [r * N_NODES + dst[i]], 1);
    }
}
__global__ void k_inv() {
    int i = blockIdx.x * blockDim.x + threadIdx.x;
    if (i < RN) {
        g_inv_out[i] = rsqrtf((float)max(g_deg_out[i], 1));
        g_inv_in [i] = rsqrtf((float)max(g_deg_in [i], 1));
    }
}
__global__ void k_scan1() {
    __shared__ int sh[1024];
    int t = threadIdx.x, g = blockIdx.x * 1024 + t;
    int v = (g < RN) ? g_deg_in[g] : 0;
    sh[t] = v; __syncthreads();
    for (int off = 1; off < 1024; off <<= 1) {
        int x = (t >= off) ? sh[t - off] : 0;
        __syncthreads(); sh[t] += x; __syncthreads();
    }
    if (g < RN) g_row_start[g] = sh[t] - v;
    if (t == 1023) g_bsum_scan[blockIdx.x] = sh[t];
}
__global__ void k_scan2(int nblk) {
    __shared__ int sh[1024];
    int t = threadIdx.x;
    int v = (t < nblk) ? g_bsum_scan[t] : 0;
    sh[t] = v; __syncthreads();
    for (int off = 1; off < 1024; off <<= 1) {
        int x = (t >= off) ? sh[t - off] : 0;
        __syncthreads(); sh[t] += x; __syncthreads();
    }
    if (t < nblk) g_bsum_scan[t] = sh[t] - v;
}
__global__ void k_scan3() {
    int i = blockIdx.x * blockDim.x + threadIdx.x;
    if (i < RN) {
        int rs = g_row_start[i] + g_bsum_scan[i >> 10];
        g_row_start[i] = rs;
        g_cursor[i]    = rs;
    }
}
__global__ void k_fill(const int* __restrict__ src, const int* __restrict__ dst) {
    int i = blockIdx.x * blockDim.x + threadIdx.x;
    if (i < TOT_E) {
        int r = i / N_EDGES;
        int s = src[i], d = dst[i];
        int pos = atomicAdd(&g_cursor[r * N_NODES + d], 1);
        g_edges[pos] = make_int2(s, __float_as_int(g_inv_out[r * N_NODES + s]));
    }
}

// ---------------- x -> fp16 (once per call) ----------------------------------
__global__ void k_cvt_x(const float4* __restrict__ x) {
    int i = blockIdx.x * blockDim.x + threadIdx.x;   // one float4 -> 4 halfs
    if (i < N_NODES * DIM / 4) {
        float4 v = x[i];
        uint2 o;
        __half2 p0 = __floats2half2_rn(v.x, v.y);
        __half2 p1 = __floats2half2_rn(v.z, v.w);
        o.x = *(uint32_t*)&p0;
        o.y = *(uint32_t*)&p1;
        ((uint2*)g_x16)[i] = o;
    }
}

// ---------------- aggregation (fp16 gather) -> split-bf16 P ------------------
// one warp per (relation, node); each lane owns 4 cols of 128 (uint2 = 4 halfs)
__global__ void k_agg(int sel) {
    const uint2* h = (sel == 0) ? (const uint2*)g_x16
                   : (sel == 1) ? (const uint2*)g_h16A
                                : (const uint2*)g_h16B;
    int wid  = (blockIdx.x * blockDim.x + threadIdx.x) >> 5;
    int lane = threadIdx.x & 31;
    if (wid >= RN) return;
    int start = g_row_start[wid];
    int len   = g_deg_in[wid];
    float4 acc = make_float4(0.f, 0.f, 0.f, 0.f);
    for (int base = 0; base < len; base += 32) {
        int rem = len - base;
        int2 e = (lane < rem) ? g_edges[start + base + lane] : make_int2(0, 0);
        int cnt = min(32, rem);
        for (int k = 0; k < cnt; k++) {
            int   s = __shfl_sync(0xffffffffu, e.x, k);
            float w = __int_as_float(__shfl_sync(0xffffffffu, e.y, k));
            uint2 v = h[s * 32 + lane];
            float2 f0 = __half22float2(*(__half2*)&v.x);
            float2 f1 = __half22float2(*(__half2*)&v.y);
            acc.x = fmaf(w, f0.x, acc.x);
            acc.y = fmaf(w, f0.y, acc.y);
            acc.z = fmaf(w, f1.x, acc.z);
            acc.w = fmaf(w, f1.y, acc.w);
        }
    }
    float si = g_inv_in[wid];
    acc.x *= si; acc.y *= si; acc.z *= si; acc.w *= si;
    int n = wid % N_NODES;
    int r = wid / N_NODES;
    __nv_bfloat16 hx0 = __float2bfloat16_rn(acc.x);
    __nv_bfloat16 hx1 = __float2bfloat16_rn(acc.y);
    __nv_bfloat16 hx2 = __float2bfloat16_rn(acc.z);
    __nv_bfloat16 hx3 = __float2bfloat16_rn(acc.w);
    __nv_bfloat16 lx0 = __float2bfloat16_rn(acc.x - __bfloat162float(hx0));
    __nv_bfloat16 lx1 = __float2bfloat16_rn(acc.y - __bfloat162float(hx1));
    __nv_bfloat16 lx2 = __float2bfloat16_rn(acc.z - __bfloat162float(hx2));
    __nv_bfloat16 lx3 = __float2bfloat16_rn(acc.w - __bfloat162float(hx3));
    uint2 hi, lo;
    hi.x = (uint32_t)__bfloat16_as_ushort(hx1) << 16 | __bfloat16_as_ushort(hx0);
    hi.y = (uint32_t)__bfloat16_as_ushort(hx3) << 16 | __bfloat16_as_ushort(hx2);
    lo.x = (uint32_t)__bfloat16_as_ushort(lx1) << 16 | __bfloat16_as_ushort(lx0);
    lo.y = (uint32_t)__bfloat16_as_ushort(lx3) << 16 | __bfloat16_as_ushort(lx2);
    int idx8 = n * 96 + r * 32 + lane;         // uint2 index into [NPAD][384]
    ((uint2*)g_Ph)[idx8] = hi;
    ((uint2*)g_Pl)[idx8] = lo;
}

// ---------------- per-layer weight prep: bf16 split + combined bias ---------
__global__ void k_prep(const float* __restrict__ W, const float* __restrict__ b, int ncols) {
    int idx = blockIdx.x * blockDim.x + threadIdx.x;   // idx = k*128 + n
    if (idx < K_DIM * 128) {
        int k = idx >> 7;
        int n = idx & 127;
        float w = (n < ncols) ? W[k * ncols + n] : 0.f;
        __nv_bfloat16 hi = __float2bfloat16_rn(w);
        g_Wh[idx] = hi;
        g_Wl[idx] = __float2bfloat16_rn(w - __bfloat162float(hi));
    }
    if (idx < 128)
        g_bias[idx] = (idx < ncols) ? b[idx] + b[ncols + idx] + b[2 * ncols + idx] : 0.f;
}

// ---------------- HMMA GEMM: C = [relu]( P @ W + bsum ) ---------------------
// 128x128 CTA tile, 8 warps of 32x64, mma.m16n8k16 bf16, 3-pass split-fp32.
// RELU=true layers write fp16 hidden (ncols=128); last layer writes fp32 d_out.
#define ASTRIDE 40    // 32 + 8 pad (bf16)
#define BSTRIDE 136   // 128 + 8 pad (bf16)
template <bool RELU>
__global__ void __launch_bounds__(256) k_gemm_mma(float* Cext, int osel, int ncols) {
    __shared__ __align__(16) __nv_bfloat16 As[128 * ASTRIDE];
    __shared__ __align__(16) __nv_bfloat16 Bs[32 * BSTRIDE];

    int t = threadIdx.x;
    int w = t >> 5, lane = t & 31;
    int wm = w & 3, wn = w >> 2;
    int row0 = blockIdx.x * 128;

    float d[2][8][4];
#pragma unroll
    for (int i = 0; i < 2; i++)
#pragma unroll
        for (int j = 0; j < 8; j++)
#pragma unroll
            for (int k = 0; k < 4; k++) d[i][j][k] = 0.f;

    int a_row = t >> 1;           // 0..127
    int a_col = (t & 1) * 16;     // 0 or 16
    int b_row = t >> 3;           // 0..31
    int b_col = (t & 7) * 16;     // 0..112

    uint32_t sA = smem_u32(As), sB = smem_u32(Bs);

    uint4 ra0, ra1, rb0, rb1;
    {
        const __nv_bfloat16* ap = g_Ph + (size_t)(row0 + a_row) * K_DIM + a_col;
        ra0 = *(const uint4*)ap; ra1 = *(const uint4*)(ap + 8);
        const __nv_bfloat16* bp = g_Wh + b_row * 128 + b_col;
        rb0 = *(const uint4*)bp; rb1 = *(const uint4*)(bp + 8);
    }

    const int NIT = 36;   // 3 passes x 12 chunks of BK=32
    for (int it = 0; it < NIT; it++) {
        *(uint4*)&As[a_row * ASTRIDE + a_col]     = ra0;
        *(uint4*)&As[a_row * ASTRIDE + a_col + 8] = ra1;
        *(uint4*)&Bs[b_row * BSTRIDE + b_col]     = rb0;
        *(uint4*)&Bs[b_row * BSTRIDE + b_col + 8] = rb1;
        __syncthreads();

        if (it + 1 < NIT) {
            int nx = it + 1;
            int p  = nx / 12;
            int kk = (nx - p * 12) * 32;
            const __nv_bfloat16* Ab = (p == 1) ? g_Pl : g_Ph;
            const __nv_bfloat16* Bb = (p == 2) ? g_Wl : g_Wh;
            const __nv_bfloat16* ap = Ab + (size_t)(row0 + a_row) * K_DIM + kk + a_col;
            ra0 = *(const uint4*)ap; ra1 = *(const uint4*)(ap + 8);
            const __nv_bfloat16* bp = Bb + (size_t)(kk + b_row) * 128 + b_col;
            rb0 = *(const uint4*)bp; rb1 = *(const uint4*)(bp + 8);
        }

#pragma unroll
        for (int kh = 0; kh < 32; kh += 16) {
            uint32_t a[2][4];
#pragma unroll
            for (int mi = 0; mi < 2; mi++) {
                uint32_t addr = sA + (uint32_t)(((wm * 32 + mi * 16 + (lane & 15)) * ASTRIDE
                                                 + kh + (lane >> 4) * 8) * 2);
                asm volatile("ldmatrix.sync.aligned.m8n8.x4.shared.b16 {%0,%1,%2,%3}, [%4];"
                    : "=r"(a[mi][0]), "=r"(a[mi][1]), "=r"(a[mi][2]), "=r"(a[mi][3]) : "r"(addr));
            }
            uint32_t bfr[8][2];
#pragma unroll
            for (int nj = 0; nj < 4; nj++) {
                uint32_t addr = sB + (uint32_t)(((kh + (lane & 15)) * BSTRIDE
                                                 + wn * 64 + nj * 16 + (lane >> 4) * 8) * 2);
                uint32_t b0, b1, b2, b3;
                asm volatile("ldmatrix.sync.aligned.m8n8.x4.trans.shared.b16 {%0,%1,%2,%3}, [%4];"
                    : "=r"(b0), "=r"(b1), "=r"(b2), "=r"(b3) : "r"(addr));
                bfr[nj * 2][0] = b0; bfr[nj * 2][1] = b1;
                bfr[nj * 2 + 1][0] = b2; bfr[nj * 2 + 1][1] = b3;
            }
#pragma unroll
            for (int mi = 0; mi < 2; mi++)
#pragma unroll
                for (int nj = 0; nj < 8; nj++)
                    asm volatile("mma.sync.aligned.m16n8k16.row.col.f32.bf16.bf16.f32 "
                        "{%0,%1,%2,%3}, {%4,%5,%6,%7}, {%8,%9}, {%0,%1,%2,%3};"
                        : "+f"(d[mi][nj][0]), "+f"(d[mi][nj][1]),
                          "+f"(d[mi][nj][2]), "+f"(d[mi][nj][3])
                        : "r"(a[mi][0]), "r"(a[mi][1]), "r"(a[mi][2]), "r"(a[mi][3]),
                          "r"(bfr[nj][0]), "r"(bfr[nj][1]));
        }
        __syncthreads();
    }

    // epilogue
    if (wn * 64 >= ncols) return;
    __half* outh = (osel == 1) ? g_h16A : g_h16B;
    int cbase = wn * 64 + (lane & 3) * 2;
#pragma unroll
    for (int mi = 0; mi < 2; mi++) {
#pragma unroll
        for (int half_ = 0; half_ < 2; half_++) {
            int row = row0 + wm * 32 + mi * 16 + (lane >> 2) + half_ * 8;
            if (row >= N_NODES) continue;
#pragma unroll
            for (int nj = 0; nj < 8; nj++) {
                int c = cbase + nj * 8;
                float v0 = d[mi][nj][half_ * 2 + 0] + g_bias[c];
                float v1 = d[mi][nj][half_ * 2 + 1] + g_bias[c + 1];
                if (RELU) {
                    v0 = fmaxf(v0, 0.f); v1 = fmaxf(v1, 0.f);
                    *(__half2*)(outh + (size_t)row * DIM + c) = __floats2half2_rn(v0, v1);
                } else {
                    *(float2*)(Cext + (size_t)row * ncols + c) = make_float2(v0, v1);
                }
            }
        }
    }
}

// ---------------- launch ----------------------------------------------------
extern "C" void kernel_launch(void* const* d_in, const int* in_sizes, int n_in,
                              void* d_out, int out_size) {
    const float* x   = (const float*)d_in[0];
    const int*   src = (const int*)d_in[1];
    const int*   dst = (const int*)d_in[2];
    const float* W[6];
    const float* b[6];
    for (int l = 0; l < 6; l++) {
        W[l] = (const float*)d_in[3 + 2 * l];
        b[l] = (const float*)d_in[4 + 2 * l];
    }

    const int T = 256;
    k_zero_deg<<<(RN + T - 1) / T, T>>>();
    k_count<<<(TOT_E + T - 1) / T, T>>>(src, dst);
    k_inv<<<(RN + T - 1) / T, T>>>();
    int nblk = (RN + 1023) / 1024;
    k_scan1<<<nblk, 1024>>>();
    k_scan2<<<1, 1024>>>(nblk);
    k_scan3<<<(RN + T - 1) / T, T>>>();
    k_fill<<<(TOT_E + T - 1) / T, T>>>(src, dst);
    k_cvt_x<<<(N_NODES * DIM / 4 + T - 1) / T, T>>>((const float4*)x);

    int agg_blocks  = (RN * 32 + T - 1) / T;
    int gemm_blocks = NPAD / 128;   // 782

    int in_sel [6] = {0, 1, 2, 1, 2, 1};
    int out_sel[6] = {1, 2, 1, 2, 1, 0};

    for (int l = 0; l < 6; l++) {
        int ncols = (l == 5) ? OUT_DIM : DIM;
        k_prep<<<(K_DIM * 128 + T - 1) / T, T>>>(W[l], b[l], ncols);
        k_agg<<<agg_blocks, T>>>(in_sel[l]);
        if (l == 5)
            k_gemm_mma<false><<<gemm_blocks, T>>>((float*)d_out, 0, ncols);
        else
            k_gemm_mma<true><<<gemm_blocks, T>>>(nullptr, out_sel[l], ncols);
    }
}

// round 6
// speedup vs baseline: 1.6909x; 1.0541x over previous
#include <cuda_runtime.h>
#include <cuda_bf16.h>
#include <cuda_fp16.h>
#include <cstdint>

// Problem constants (fixed by setup_inputs)
#define N_NODES 100000
#define NPAD    100096               // 782 * 128 (padded M for GEMM tiles)
#define N_REL   3
#define N_EDGES 1600000
#define DIM     128
#define OUT_DIM 64
#define K_DIM   (N_REL * DIM)        // 384
#define RN      (N_REL * N_NODES)    // 300000
#define TOT_E   (N_REL * N_EDGES)    // 4800000

// ---------------- scratch (device globals; zero-initialized) ----------------
__device__ int   g_deg_out[RN];
__device__ int   g_deg_in[RN];
__device__ float g_inv_out[RN];
__device__ float g_inv_in[RN];
__device__ int   g_row_start[RN];
__device__ int   g_cursor[RN];
__device__ int   g_bsum_scan[1024];
__device__ int2  g_edges[TOT_E];             // {src, bits(inv_out[src])}
__device__ __align__(16) __half g_x16[N_NODES * DIM];   // fp16 input features
__device__ __align__(16) __half g_h16A[N_NODES * DIM];  // fp16 hidden A
__device__ __align__(16) __half g_h16B[N_NODES * DIM];  // fp16 hidden B
__device__ __nv_bfloat16 g_Ph[NPAD * K_DIM]; // split-hi of aggregated features
__device__ __nv_bfloat16 g_Pl[NPAD * K_DIM]; // split-lo
__device__ __nv_bfloat16 g_Wh[K_DIM * 128];  // W hi  [384][128] (cols zero-padded)
__device__ __nv_bfloat16 g_Wl[K_DIM * 128];  // W lo
__device__ float g_bias[128];                // sum_r b_r, padded

__device__ __forceinline__ uint32_t smem_u32(const void* p) {
    uint32_t a;
    asm("{ .reg .u64 t; cvta.to.shared.u64 t, %1; cvt.u32.u64 %0, t; }" : "=r"(a) : "l"(p));
    return a;
}
#define CP16(dst, src) \
    asm volatile("cp.async.ca.shared.global [%0], [%1], 16;" :: "r"(dst), "l"(src))
#define CP_COMMIT() asm volatile("cp.async.commit_group;" ::: "memory")
#define CP_WAIT1()  asm volatile("cp.async.wait_group 1;" ::: "memory")

// ---------------- CSR build -------------------------------------------------
__global__ void k_zero_deg() {
    int i = blockIdx.x * blockDim.x + threadIdx.x;
    if (i < RN) { g_deg_out[i] = 0; g_deg_in[i] = 0; }
}
__global__ void k_count(const int* __restrict__ src, const int* __restrict__ dst) {
    int i = blockIdx.x * blockDim.x + threadIdx.x;
    if (i < TOT_E) {
        int r = i / N_EDGES;
        atomicAdd(&g_deg_out[r * N_NODES + src[i]], 1);
        atomicAdd(&g_deg_in [r * N_NODES + dst[i]], 1);
    }
}
__global__ void k_scan1() {
    __shared__ int sh[1024];
    int t = threadIdx.x, g = blockIdx.x * 1024 + t;
    int v = (g < RN) ? g_deg_in[g] : 0;
    sh[t] = v; __syncthreads();
    for (int off = 1; off < 1024; off <<= 1) {
        int x = (t >= off) ? sh[t - off] : 0;
        __syncthreads(); sh[t] += x; __syncthreads();
    }
    if (g < RN) g_row_start[g] = sh[t] - v;
    if (t == 1023) g_bsum_scan[blockIdx.x] = sh[t];
}
__global__ void k_scan2(int nblk) {
    __shared__ int sh[1024];
    int t = threadIdx.x;
    int v = (t < nblk) ? g_bsum_scan[t] : 0;
    sh[t] = v; __syncthreads();
    for (int off = 1; off < 1024; off <<= 1) {
        int x = (t >= off) ? sh[t - off] : 0;
        __syncthreads(); sh[t] += x; __syncthreads();
    }
    if (t < nblk) g_bsum_scan[t] = sh[t] - v;
}
// scan finalize + inverse-degree norms (fused)
__global__ void k_scan3() {
    int i = blockIdx.x * blockDim.x + threadIdx.x;
    if (i < RN) {
        int rs = g_row_start[i] + g_bsum_scan[i >> 10];
        g_row_start[i] = rs;
        g_cursor[i]    = rs;
        g_inv_out[i] = rsqrtf((float)max(g_deg_out[i], 1));
        g_inv_in [i] = rsqrtf((float)max(g_deg_in [i], 1));
    }
}
__global__ void k_fill(const int* __restrict__ src, const int* __restrict__ dst) {
    int i = blockIdx.x * blockDim.x + threadIdx.x;
    if (i < TOT_E) {
        int r = i / N_EDGES;
        int s = src[i], d = dst[i];
        int pos = atomicAdd(&g_cursor[r * N_NODES + d], 1);
        g_edges[pos] = make_int2(s, __float_as_int(g_inv_out[r * N_NODES + s]));
    }
}

// ---------------- x -> fp16 (once per call) ----------------------------------
__global__ void k_cvt_x(const float4* __restrict__ x) {
    int i = blockIdx.x * blockDim.x + threadIdx.x;   // one float4 -> 4 halfs
    if (i < N_NODES * DIM / 4) {
        float4 v = x[i];
        uint2 o;
        __half2 p0 = __floats2half2_rn(v.x, v.y);
        __half2 p1 = __floats2half2_rn(v.z, v.w);
        o.x = *(uint32_t*)&p0;
        o.y = *(uint32_t*)&p1;
        ((uint2*)g_x16)[i] = o;
    }
}

// ---------------- aggregation (fp16 gather) -> split-bf16 P ------------------
// one warp per (relation, node); warp-uniform edge loads, 2x unroll
__global__ void k_agg(int sel) {
    const uint2* __restrict__ h = (sel == 0) ? (const uint2*)g_x16
                                : (sel == 1) ? (const uint2*)g_h16A
                                             : (const uint2*)g_h16B;
    int wid  = (blockIdx.x * blockDim.x + threadIdx.x) >> 5;
    int lane = threadIdx.x & 31;
    if (wid >= RN) return;
    int start = g_row_start[wid];
    int len   = g_deg_in[wid];
    const int2* __restrict__ ep = g_edges + start;
    float4 acc = make_float4(0.f, 0.f, 0.f, 0.f);
    int k = 0;
    for (; k + 2 <= len; k += 2) {
        int2 e0 = ep[k];
        int2 e1 = ep[k + 1];
        uint2 v0 = h[e0.x * 32 + lane];
        uint2 v1 = h[e1.x * 32 + lane];
        float w0 = __int_as_float(e0.y);
        float w1 = __int_as_float(e1.y);
        float2 a0 = __half22float2(*(__half2*)&v0.x);
        float2 a1 = __half22float2(*(__half2*)&v0.y);
        float2 b0 = __half22float2(*(__half2*)&v1.x);
        float2 b1 = __half22float2(*(__half2*)&v1.y);
        acc.x = fmaf(w0, a0.x, acc.x); acc.y = fmaf(w0, a0.y, acc.y);
        acc.z = fmaf(w0, a1.x, acc.z); acc.w = fmaf(w0, a1.y, acc.w);
        acc.x = fmaf(w1, b0.x, acc.x); acc.y = fmaf(w1, b0.y, acc.y);
        acc.z = fmaf(w1, b1.x, acc.z); acc.w = fmaf(w1, b1.y, acc.w);
    }
    if (k < len) {
        int2 e0 = ep[k];
        uint2 v0 = h[e0.x * 32 + lane];
        float w0 = __int_as_float(e0.y);
        float2 a0 = __half22float2(*(__half2*)&v0.x);
        float2 a1 = __half22float2(*(__half2*)&v0.y);
        acc.x = fmaf(w0, a0.x, acc.x); acc.y = fmaf(w0, a0.y, acc.y);
        acc.z = fmaf(w0, a1.x, acc.z); acc.w = fmaf(w0, a1.y, acc.w);
    }
    float si = g_inv_in[wid];
    acc.x *= si; acc.y *= si; acc.z *= si; acc.w *= si;
    int n = wid % N_NODES;
    int r = wid / N_NODES;
    __nv_bfloat16 hx0 = __float2bfloat16_rn(acc.x);
    __nv_bfloat16 hx1 = __float2bfloat16_rn(acc.y);
    __nv_bfloat16 hx2 = __float2bfloat16_rn(acc.z);
    __nv_bfloat16 hx3 = __float2bfloat16_rn(acc.w);
    __nv_bfloat16 lx0 = __float2bfloat16_rn(acc.x - __bfloat162float(hx0));
    __nv_bfloat16 lx1 = __float2bfloat16_rn(acc.y - __bfloat162float(hx1));
    __nv_bfloat16 lx2 = __float2bfloat16_rn(acc.z - __bfloat162float(hx2));
    __nv_bfloat16 lx3 = __float2bfloat16_rn(acc.w - __bfloat162float(hx3));
    uint2 hi, lo;
    hi.x = (uint32_t)__bfloat16_as_ushort(hx1) << 16 | __bfloat16_as_ushort(hx0);
    hi.y = (uint32_t)__bfloat16_as_ushort(hx3) << 16 | __bfloat16_as_ushort(hx2);
    lo.x = (uint32_t)__bfloat16_as_ushort(lx1) << 16 | __bfloat16_as_ushort(lx0);
    lo.y = (uint32_t)__bfloat16_as_ushort(lx3) << 16 | __bfloat16_as_ushort(lx2);
    int idx8 = n * 96 + r * 32 + lane;         // uint2 index into [NPAD][384]
    ((uint2*)g_Ph)[idx8] = hi;
    ((uint2*)g_Pl)[idx8] = lo;
}

// ---------------- per-layer weight prep: bf16 split + combined bias ---------
__global__ void k_prep(const float* __restrict__ W, const float* __restrict__ b, int ncols) {
    int idx = blockIdx.x * blockDim.x + threadIdx.x;   // idx = k*128 + n
    if (idx < K_DIM * 128) {
        int k = idx >> 7;
        int n = idx & 127;
        float w = (n < ncols) ? W[k * ncols + n] : 0.f;
        __nv_bfloat16 hi = __float2bfloat16_rn(w);
        g_Wh[idx] = hi;
        g_Wl[idx] = __float2bfloat16_rn(w - __bfloat162float(hi));
    }
    if (idx < 128)
        g_bias[idx] = (idx < ncols) ? b[idx] + b[ncols + idx] + b[2 * ncols + idx] : 0.f;
}

// ---------------- HMMA GEMM: C = [relu]( P @ W + bsum ) ---------------------
// 128x128 CTA tile, 8 warps of 32x64, mma.m16n8k16 bf16, 3-pass split-fp32.
// 3-stage cp.async pipeline, one __syncthreads per K-chunk.
#define ASTRIDE 40    // 32 + 8 pad (bf16)
#define BSTRIDE 136   // 128 + 8 pad (bf16)
#define ABYTES  (128 * ASTRIDE * 2)        // 10240
#define BBYTES  (32 * BSTRIDE * 2)         // 8704
#define STG     (ABYTES + BBYTES)          // 18944
#define GEMM_SMEM (3 * STG)                // 56832
#define NIT 36        // 3 passes x 12 chunks of BK=32

__device__ __forceinline__ void gemm_load_stage(uint32_t sbase, int s, int slot, int row0,
                                                int a_row, int a_col, int b_row, int b_col) {
    int p  = s / 12;
    int kk = (s - p * 12) * 32;
    const __nv_bfloat16* Ab = (p == 1) ? g_Pl : g_Ph;
    const __nv_bfloat16* Bb = (p == 2) ? g_Wl : g_Wh;
    const __nv_bfloat16* ap = Ab + (size_t)(row0 + a_row) * K_DIM + kk + a_col;
    const __nv_bfloat16* bp = Bb + (size_t)(kk + b_row) * 128 + b_col;
    uint32_t da = sbase + slot * STG + (a_row * ASTRIDE + a_col) * 2;
    uint32_t db = sbase + slot * STG + ABYTES + (b_row * BSTRIDE + b_col) * 2;
    CP16(da,      ap);
    CP16(da + 16, ap + 8);
    CP16(db,      bp);
    CP16(db + 16, bp + 8);
}

template <bool RELU>
__global__ void __launch_bounds__(256) k_gemm_mma(float* Cext, int osel, int ncols) {
    extern __shared__ __align__(16) char smem[];
    uint32_t sbase = smem_u32(smem);

    int t = threadIdx.x;
    int w = t >> 5, lane = t & 31;
    int wm = w & 3, wn = w >> 2;
    int row0 = blockIdx.x * 128;

    float d[2][8][4];
#pragma unroll
    for (int i = 0; i < 2; i++)
#pragma unroll
        for (int j = 0; j < 8; j++)
#pragma unroll
            for (int k = 0; k < 4; k++) d[i][j][k] = 0.f;

    int a_row = t >> 1;           // 0..127
    int a_col = (t & 1) * 16;     // 0 or 16
    int b_row = t >> 3;           // 0..31
    int b_col = (t & 7) * 16;     // 0..112

    gemm_load_stage(sbase, 0, 0, row0, a_row, a_col, b_row, b_col); CP_COMMIT();
    gemm_load_stage(sbase, 1, 1, row0, a_row, a_col, b_row, b_col); CP_COMMIT();

    int slot = 0, slot2 = 2;
    for (int it = 0; it < NIT; it++) {
        CP_WAIT1();
        __syncthreads();
        if (it + 2 < NIT)
            gemm_load_stage(sbase, it + 2, slot2, row0, a_row, a_col, b_row, b_col);
        CP_COMMIT();

        uint32_t sA = sbase + slot * STG;
        uint32_t sB = sA + ABYTES;
#pragma unroll
        for (int kh = 0; kh < 32; kh += 16) {
            uint32_t a[2][4];
#pragma unroll
            for (int mi = 0; mi < 2; mi++) {
                uint32_t addr = sA + (uint32_t)(((wm * 32 + mi * 16 + (lane & 15)) * ASTRIDE
                                                 + kh + (lane >> 4) * 8) * 2);
                asm volatile("ldmatrix.sync.aligned.m8n8.x4.shared.b16 {%0,%1,%2,%3}, [%4];"
                    : "=r"(a[mi][0]), "=r"(a[mi][1]), "=r"(a[mi][2]), "=r"(a[mi][3]) : "r"(addr));
            }
            uint32_t bfr[8][2];
#pragma unroll
            for (int nj = 0; nj < 4; nj++) {
                uint32_t addr = sB + (uint32_t)(((kh + (lane & 15)) * BSTRIDE
                                                 + wn * 64 + nj * 16 + (lane >> 4) * 8) * 2);
                uint32_t b0, b1, b2, b3;
                asm volatile("ldmatrix.sync.aligned.m8n8.x4.trans.shared.b16 {%0,%1,%2,%3}, [%4];"
                    : "=r"(b0), "=r"(b1), "=r"(b2), "=r"(b3) : "r"(addr));
                bfr[nj * 2][0] = b0; bfr[nj * 2][1] = b1;
                bfr[nj * 2 + 1][0] = b2; bfr[nj * 2 + 1][1] = b3;
            }
#pragma unroll
            for (int mi = 0; mi < 2; mi++)
#pragma unroll
                for (int nj = 0; nj < 8; nj++)
                    asm volatile("mma.sync.aligned.m16n8k16.row.col.f32.bf16.bf16.f32 "
                        "{%0,%1,%2,%3}, {%4,%5,%6,%7}, {%8,%9}, {%0,%1,%2,%3};"
                        : "+f"(d[mi][nj][0]), "+f"(d[mi][nj][1]),
                          "+f"(d[mi][nj][2]), "+f"(d[mi][nj][3])
                        : "r"(a[mi][0]), "r"(a[mi][1]), "r"(a[mi][2]), "r"(a[mi][3]),
                          "r"(bfr[nj][0]), "r"(bfr[nj][1]));
        }
        slot  = (slot  == 2) ? 0 : slot + 1;
        slot2 = (slot2 == 2) ? 0 : slot2 + 1;
    }

    // epilogue
    if (wn * 64 >= ncols) return;
    __half* outh = (osel == 1) ? g_h16A : g_h16B;
    int cbase = wn * 64 + (lane & 3) * 2;
#pragma unroll
    for (int mi = 0; mi < 2; mi++) {
#pragma unroll
        for (int half_ = 0; half_ < 2; half_++) {
            int row = row0 + wm * 32 + mi * 16 + (lane >> 2) + half_ * 8;
            if (row >= N_NODES) continue;
#pragma unroll
            for (int nj = 0; nj < 8; nj++) {
                int c = cbase + nj * 8;
                float v0 = d[mi][nj][half_ * 2 + 0] + g_bias[c];
                float v1 = d[mi][nj][half_ * 2 + 1] + g_bias[c + 1];
                if (RELU) {
                    v0 = fmaxf(v0, 0.f); v1 = fmaxf(v1, 0.f);
                    *(__half2*)(outh + (size_t)row * DIM + c) = __floats2half2_rn(v0, v1);
                } else {
                    *(float2*)(Cext + (size_t)row * ncols + c) = make_float2(v0, v1);
                }
            }
        }
    }
}

// ---------------- launch ----------------------------------------------------
extern "C" void kernel_launch(void* const* d_in, const int* in_sizes, int n_in,
                              void* d_out, int out_size) {
    const float* x   = (const float*)d_in[0];
    const int*   src = (const int*)d_in[1];
    const int*   dst = (const int*)d_in[2];
    const float* W[6];
    const float* b[6];
    for (int l = 0; l < 6; l++) {
        W[l] = (const float*)d_in[3 + 2 * l];
        b[l] = (const float*)d_in[4 + 2 * l];
    }

    cudaFuncSetAttribute(k_gemm_mma<true>,  cudaFuncAttributeMaxDynamicSharedMemorySize, GEMM_SMEM);
    cudaFuncSetAttribute(k_gemm_mma<false>, cudaFuncAttributeMaxDynamicSharedMemorySize, GEMM_SMEM);

    const int T = 256;
    k_zero_deg<<<(RN + T - 1) / T, T>>>();
    k_count<<<(TOT_E + T - 1) / T, T>>>(src, dst);
    int nblk = (RN + 1023) / 1024;
    k_scan1<<<nblk, 1024>>>();
    k_scan2<<<1, 1024>>>(nblk);
    k_scan3<<<(RN + T - 1) / T, T>>>();
    k_fill<<<(TOT_E + T - 1) / T, T>>>(src, dst);
    k_cvt_x<<<(N_NODES * DIM / 4 + T - 1) / T, T>>>((const float4*)x);

    int agg_blocks  = (RN * 32 + T - 1) / T;
    int gemm_blocks = NPAD / 128;   // 782

    int in_sel [6] = {0, 1, 2, 1, 2, 1};
    int out_sel[6] = {1, 2, 1, 2, 1, 0};

    for (int l = 0; l < 6; l++) {
        int ncols = (l == 5) ? OUT_DIM : DIM;
        k_prep<<<(K_DIM * 128 + T - 1) / T, T>>>(W[l], b[l], ncols);
        k_agg<<<agg_blocks, T>>>(in_sel[l]);
        if (l == 5)
            k_gemm_mma<false><<<gemm_blocks, T, GEMM_SMEM>>>((float*)d_out, 0, ncols);
        else
            k_gemm_mma<true><<<gemm_blocks, T, GEMM_SMEM>>>(nullptr, out_sel[l], ncols);
    }
}

// round 7
// speedup vs baseline: 1.9819x; 1.1720x over previous
#include <cuda_runtime.h>
#include <cuda_bf16.h>
#include <cuda_fp16.h>
#include <cstdint>

// Problem constants (fixed by setup_inputs)
#define N_NODES 100000
#define NPAD    100096               // 782 * 128 (padded M for GEMM tiles)
#define N_REL   3
#define N_EDGES 1600000
#define DIM     128
#define OUT_DIM 64
#define K_DIM   (N_REL * DIM)        // 384
#define RN      (N_REL * N_NODES)    // 300000
#define TOT_E   (N_REL * N_EDGES)    // 4800000

// ---------------- scratch (device globals; zero-initialized) ----------------
__device__ int   g_deg_out[RN];
__device__ int   g_deg_in[RN];
__device__ float g_inv_out[RN];
__device__ float g_inv_in[RN];
__device__ int   g_row_start[RN];
__device__ int   g_cursor[RN];
__device__ int   g_bsum_scan[1024];
__device__ int2  g_edges[TOT_E];             // {src, bits(inv_out[src])}
__device__ __align__(16) __half g_x16[N_NODES * DIM];   // fp16 input features
__device__ __align__(16) __half g_h16A[N_NODES * DIM];  // fp16 hidden A
__device__ __align__(16) __half g_h16B[N_NODES * DIM];  // fp16 hidden B
__device__ __align__(16) __half g_P16[NPAD * K_DIM];    // aggregated features (fp16)
__device__ __align__(16) __half g_Wh[K_DIM * 128];      // W hi  [384][128] (cols zero-padded)
__device__ __align__(16) __half g_Wl[K_DIM * 128];      // W lo (residual)
__device__ float g_bias[128];                           // sum_r b_r, padded

__device__ __forceinline__ uint32_t smem_u32(const void* p) {
    uint32_t a;
    asm("{ .reg .u64 t; cvta.to.shared.u64 t, %1; cvt.u32.u64 %0, t; }" : "=r"(a) : "l"(p));
    return a;
}
#define CP16(dst, src) \
    asm volatile("cp.async.ca.shared.global [%0], [%1], 16;" :: "r"(dst), "l"(src))
#define CP_COMMIT() asm volatile("cp.async.commit_group;" ::: "memory")
#define CP_WAIT1()  asm volatile("cp.async.wait_group 1;" ::: "memory")

// ---------------- CSR build -------------------------------------------------
__global__ void k_zero_deg() {
    int i = blockIdx.x * blockDim.x + threadIdx.x;
    if (i < RN) { g_deg_out[i] = 0; g_deg_in[i] = 0; }
}
__global__ void k_count(const int* __restrict__ src, const int* __restrict__ dst) {
    int i = blockIdx.x * blockDim.x + threadIdx.x;
    if (i < TOT_E) {
        int r = i / N_EDGES;
        atomicAdd(&g_deg_out[r * N_NODES + src[i]], 1);
        atomicAdd(&g_deg_in [r * N_NODES + dst[i]], 1);
    }
}
__global__ void k_scan1() {
    __shared__ int sh[1024];
    int t = threadIdx.x, g = blockIdx.x * 1024 + t;
    int v = (g < RN) ? g_deg_in[g] : 0;
    sh[t] = v; __syncthreads();
    for (int off = 1; off < 1024; off <<= 1) {
        int x = (t >= off) ? sh[t - off] : 0;
        __syncthreads(); sh[t] += x; __syncthreads();
    }
    if (g < RN) g_row_start[g] = sh[t] - v;
    if (t == 1023) g_bsum_scan[blockIdx.x] = sh[t];
}
__global__ void k_scan2(int nblk) {
    __shared__ int sh[1024];
    int t = threadIdx.x;
    int v = (t < nblk) ? g_bsum_scan[t] : 0;
    sh[t] = v; __syncthreads();
    for (int off = 1; off < 1024; off <<= 1) {
        int x = (t >= off) ? sh[t - off] : 0;
        __syncthreads(); sh[t] += x; __syncthreads();
    }
    if (t < nblk) g_bsum_scan[t] = sh[t] - v;
}
// scan finalize + inverse-degree norms (fused)
__global__ void k_scan3() {
    int i = blockIdx.x * blockDim.x + threadIdx.x;
    if (i < RN) {
        int rs = g_row_start[i] + g_bsum_scan[i >> 10];
        g_row_start[i] = rs;
        g_cursor[i]    = rs;
        g_inv_out[i] = rsqrtf((float)max(g_deg_out[i], 1));
        g_inv_in [i] = rsqrtf((float)max(g_deg_in [i], 1));
    }
}
__global__ void k_fill(const int* __restrict__ src, const int* __restrict__ dst) {
    int i = blockIdx.x * blockDim.x + threadIdx.x;
    if (i < TOT_E) {
        int r = i / N_EDGES;
        int s = src[i], d = dst[i];
        int pos = atomicAdd(&g_cursor[r * N_NODES + d], 1);
        g_edges[pos] = make_int2(s, __float_as_int(g_inv_out[r * N_NODES + s]));
    }
}

// ---------------- x -> fp16 (once per call) ----------------------------------
__global__ void k_cvt_x(const float4* __restrict__ x) {
    int i = blockIdx.x * blockDim.x + threadIdx.x;   // one float4 -> 4 halfs
    if (i < N_NODES * DIM / 4) {
        float4 v = x[i];
        uint2 o;
        __half2 p0 = __floats2half2_rn(v.x, v.y);
        __half2 p1 = __floats2half2_rn(v.z, v.w);
        o.x = *(uint32_t*)&p0;
        o.y = *(uint32_t*)&p1;
        ((uint2*)g_x16)[i] = o;
    }
}

// ---------------- aggregation (fp16 gather) -> fp16 P ------------------------
// one warp per (relation, node); warp-uniform edge loads, 2x unroll
__global__ void k_agg(int sel) {
    const uint2* __restrict__ h = (sel == 0) ? (const uint2*)g_x16
                                : (sel == 1) ? (const uint2*)g_h16A
                                             : (const uint2*)g_h16B;
    int wid  = (blockIdx.x * blockDim.x + threadIdx.x) >> 5;
    int lane = threadIdx.x & 31;
    if (wid >= RN) return;
    int start = g_row_start[wid];
    int len   = g_deg_in[wid];
    const int2* __restrict__ ep = g_edges + start;
    float4 acc = make_float4(0.f, 0.f, 0.f, 0.f);
    int k = 0;
    for (; k + 2 <= len; k += 2) {
        int2 e0 = ep[k];
        int2 e1 = ep[k + 1];
        uint2 v0 = h[e0.x * 32 + lane];
        uint2 v1 = h[e1.x * 32 + lane];
        float w0 = __int_as_float(e0.y);
        float w1 = __int_as_float(e1.y);
        float2 a0 = __half22float2(*(__half2*)&v0.x);
        float2 a1 = __half22float2(*(__half2*)&v0.y);
        float2 b0 = __half22float2(*(__half2*)&v1.x);
        float2 b1 = __half22float2(*(__half2*)&v1.y);
        acc.x = fmaf(w0, a0.x, acc.x); acc.y = fmaf(w0, a0.y, acc.y);
        acc.z = fmaf(w0, a1.x, acc.z); acc.w = fmaf(w0, a1.y, acc.w);
        acc.x = fmaf(w1, b0.x, acc.x); acc.y = fmaf(w1, b0.y, acc.y);
        acc.z = fmaf(w1, b1.x, acc.z); acc.w = fmaf(w1, b1.y, acc.w);
    }
    if (k < len) {
        int2 e0 = ep[k];
        uint2 v0 = h[e0.x * 32 + lane];
        float w0 = __int_as_float(e0.y);
        float2 a0 = __half22float2(*(__half2*)&v0.x);
        float2 a1 = __half22float2(*(__half2*)&v0.y);
        acc.x = fmaf(w0, a0.x, acc.x); acc.y = fmaf(w0, a0.y, acc.y);
        acc.z = fmaf(w0, a1.x, acc.z); acc.w = fmaf(w0, a1.y, acc.w);
    }
    float si = g_inv_in[wid];
    acc.x *= si; acc.y *= si; acc.z *= si; acc.w *= si;
    int n = wid % N_NODES;
    int r = wid / N_NODES;
    uint2 o;
    __half2 p0 = __floats2half2_rn(acc.x, acc.y);
    __half2 p1 = __floats2half2_rn(acc.z, acc.w);
    o.x = *(uint32_t*)&p0;
    o.y = *(uint32_t*)&p1;
    int idx8 = n * 96 + r * 32 + lane;         // uint2 index into [NPAD][384]
    ((uint2*)g_P16)[idx8] = o;
}

// ---------------- per-layer weight prep: fp16 split + combined bias ---------
__global__ void k_prep(const float* __restrict__ W, const float* __restrict__ b, int ncols) {
    int idx = blockIdx.x * blockDim.x + threadIdx.x;   // idx = k*128 + n
    if (idx < K_DIM * 128) {
        int k = idx >> 7;
        int n = idx & 127;
        float w = (n < ncols) ? W[k * ncols + n] : 0.f;
        __half hi = __float2half_rn(w);
        g_Wh[idx] = hi;
        g_Wl[idx] = __float2half_rn(w - __half2float(hi));
    }
    if (idx < 128)
        g_bias[idx] = (idx < ncols) ? b[idx] + b[ncols + idx] + b[2 * ncols + idx] : 0.f;
}

// ---------------- HMMA GEMM: C = [relu]( P @ (Wh+Wl) + bsum ) ----------------
// 128x128 CTA tile, 8 warps of 32x64, mma.m16n8k16 fp16.
// 12 K-chunks of 32; per chunk: D += A*Wh_k + A*Wl_k. 3-stage cp.async pipeline.
#define ASTRIDE 40    // 32 + 8 pad (fp16)
#define BSTRIDE 136   // 128 + 8 pad (fp16)
#define ABYTES  (128 * ASTRIDE * 2)        // 10240
#define BBYTES  (32 * BSTRIDE * 2)         // 8704
#define STG     (ABYTES + 2 * BBYTES)      // 27648
#define GEMM_SMEM (3 * STG)                // 82944
#define NIT 12

__device__ __forceinline__ void gemm_load_stage(uint32_t sbase, int s, int slot, int row0,
                                                int a_row, int a_col, int b_row, int b_col) {
    int kk = s * 32;
    const __half* ap = g_P16 + (size_t)(row0 + a_row) * K_DIM + kk + a_col;
    const __half* bh = g_Wh + (size_t)(kk + b_row) * 128 + b_col;
    const __half* bl = g_Wl + (size_t)(kk + b_row) * 128 + b_col;
    uint32_t da  = sbase + slot * STG + (a_row * ASTRIDE + a_col) * 2;
    uint32_t dbh = sbase + slot * STG + ABYTES + (b_row * BSTRIDE + b_col) * 2;
    uint32_t dbl = dbh + BBYTES;
    CP16(da,       ap);
    CP16(da + 16,  ap + 8);
    CP16(dbh,      bh);
    CP16(dbh + 16, bh + 8);
    CP16(dbl,      bl);
    CP16(dbl + 16, bl + 8);
}

template <bool RELU>
__global__ void __launch_bounds__(256) k_gemm_mma(float* Cext, int osel, int ncols) {
    extern __shared__ __align__(16) char smem[];
    uint32_t sbase = smem_u32(smem);

    int t = threadIdx.x;
    int w = t >> 5, lane = t & 31;
    int wm = w & 3, wn = w >> 2;
    int row0 = blockIdx.x * 128;

    float d[2][8][4];
#pragma unroll
    for (int i = 0; i < 2; i++)
#pragma unroll
        for (int j = 0; j < 8; j++)
#pragma unroll
            for (int k = 0; k < 4; k++) d[i][j][k] = 0.f;

    int a_row = t >> 1;           // 0..127
    int a_col = (t & 1) * 16;     // 0 or 16
    int b_row = t >> 3;           // 0..31
    int b_col = (t & 7) * 16;     // 0..112

    gemm_load_stage(sbase, 0, 0, row0, a_row, a_col, b_row, b_col); CP_COMMIT();
    gemm_load_stage(sbase, 1, 1, row0, a_row, a_col, b_row, b_col); CP_COMMIT();

    int slot = 0, slot2 = 2;
    for (int it = 0; it < NIT; it++) {
        CP_WAIT1();
        __syncthreads();
        if (it + 2 < NIT)
            gemm_load_stage(sbase, it + 2, slot2, row0, a_row, a_col, b_row, b_col);
        CP_COMMIT();

        uint32_t sA = sbase + slot * STG;
        uint32_t sB = sA + ABYTES;
#pragma unroll
        for (int kh = 0; kh < 32; kh += 16) {
            uint32_t a[2][4];
#pragma unroll
            for (int mi = 0; mi < 2; mi++) {
                uint32_t addr = sA + (uint32_t)(((wm * 32 + mi * 16 + (lane & 15)) * ASTRIDE
                                                 + kh + (lane >> 4) * 8) * 2);
                asm volatile("ldmatrix.sync.aligned.m8n8.x4.shared.b16 {%0,%1,%2,%3}, [%4];"
                    : "=r"(a[mi][0]), "=r"(a[mi][1]), "=r"(a[mi][2]), "=r"(a[mi][3]) : "r"(addr));
            }
#pragma unroll
            for (int pass = 0; pass < 2; pass++) {
                uint32_t sBp = sB + pass * BBYTES;
                uint32_t bfr[8][2];
#pragma unroll
                for (int nj = 0; nj < 4; nj++) {
                    uint32_t addr = sBp + (uint32_t)(((kh + (lane & 15)) * BSTRIDE
                                                     + wn * 64 + nj * 16 + (lane >> 4) * 8) * 2);
                    uint32_t b0, b1, b2, b3;
                    asm volatile("ldmatrix.sync.aligned.m8n8.x4.trans.shared.b16 {%0,%1,%2,%3}, [%4];"
                        : "=r"(b0), "=r"(b1), "=r"(b2), "=r"(b3) : "r"(addr));
                    bfr[nj * 2][0] = b0; bfr[nj * 2][1] = b1;
                    bfr[nj * 2 + 1][0] = b2; bfr[nj * 2 + 1][1] = b3;
                }
#pragma unroll
                for (int mi = 0; mi < 2; mi++)
#pragma unroll
                    for (int nj = 0; nj < 8; nj++)
                        asm volatile("mma.sync.aligned.m16n8k16.row.col.f32.f16.f16.f32 "
                            "{%0,%1,%2,%3}, {%4,%5,%6,%7}, {%8,%9}, {%0,%1,%2,%3};"
                            : "+f"(d[mi][nj][0]), "+f"(d[mi][nj][1]),
                              "+f"(d[mi][nj][2]), "+f"(d[mi][nj][3])
                            : "r"(a[mi][0]), "r"(a[mi][1]), "r"(a[mi][2]), "r"(a[mi][3]),
                              "r"(bfr[nj][0]), "r"(bfr[nj][1]));
            }
        }
        slot  = (slot  == 2) ? 0 : slot + 1;
        slot2 = (slot2 == 2) ? 0 : slot2 + 1;
    }

    // epilogue
    if (wn * 64 >= ncols) return;
    __half* outh = (osel == 1) ? g_h16A : g_h16B;
    int cbase = wn * 64 + (lane & 3) * 2;
#pragma unroll
    for (int mi = 0; mi < 2; mi++) {
#pragma unroll
        for (int half_ = 0; half_ < 2; half_++) {
            int row = row0 + wm * 32 + mi * 16 + (lane >> 2) + half_ * 8;
            if (row >= N_NODES) continue;
#pragma unroll
            for (int nj = 0; nj < 8; nj++) {
                int c = cbase + nj * 8;
                float v0 = d[mi][nj][half_ * 2 + 0] + g_bias[c];
                float v1 = d[mi][nj][half_ * 2 + 1] + g_bias[c + 1];
                if (RELU) {
                    v0 = fmaxf(v0, 0.f); v1 = fmaxf(v1, 0.f);
                    *(__half2*)(outh + (size_t)row * DIM + c) = __floats2half2_rn(v0, v1);
                } else {
                    *(float2*)(Cext + (size_t)row * ncols + c) = make_float2(v0, v1);
                }
            }
        }
    }
}

// ---------------- launch ----------------------------------------------------
extern "C" void kernel_launch(void* const* d_in, const int* in_sizes, int n_in,
                              void* d_out, int out_size) {
    const float* x   = (const float*)d_in[0];
    const int*   src = (const int*)d_in[1];
    const int*   dst = (const int*)d_in[2];
    const float* W[6];
    const float* b[6];
    for (int l = 0; l < 6; l++) {
        W[l] = (const float*)d_in[3 + 2 * l];
        b[l] = (const float*)d_in[4 + 2 * l];
    }

    cudaFuncSetAttribute(k_gemm_mma<true>,  cudaFuncAttributeMaxDynamicSharedMemorySize, GEMM_SMEM);
    cudaFuncSetAttribute(k_gemm_mma<false>, cudaFuncAttributeMaxDynamicSharedMemorySize, GEMM_SMEM);

    const int T = 256;
    k_zero_deg<<<(RN + T - 1) / T, T>>>();
    k_count<<<(TOT_E + T - 1) / T, T>>>(src, dst);
    int nblk = (RN + 1023) / 1024;
    k_scan1<<<nblk, 1024>>>();
    k_scan2<<<1, 1024>>>(nblk);
    k_scan3<<<(RN + T - 1) / T, T>>>();
    k_fill<<<(TOT_E + T - 1) / T, T>>>(src, dst);
    k_cvt_x<<<(N_NODES * DIM / 4 + T - 1) / T, T>>>((const float4*)x);

    int agg_blocks  = (RN * 32 + T - 1) / T;
    int gemm_blocks = NPAD / 128;   // 782

    int in_sel [6] = {0, 1, 2, 1, 2, 1};
    int out_sel[6] = {1, 2, 1, 2, 1, 0};

    for (int l = 0; l < 6; l++) {
        int ncols = (l == 5) ? OUT_DIM : DIM;
        k_prep<<<(K_DIM * 128 + T - 1) / T, T>>>(W[l], b[l], ncols);
        k_agg<<<agg_blocks, T>>>(in_sel[l]);
        if (l == 5)
            k_gemm_mma<false><<<gemm_blocks, T, GEMM_SMEM>>>((float*)d_out, 0, ncols);
        else
            k_gemm_mma<true><<<gemm_blocks, T, GEMM_SMEM>>>(nullptr, out_sel[l], ncols);
    }
}

// round 8
// speedup vs baseline: 2.8404x; 1.4332x over previous
#include <cuda_runtime.h>
#include <cuda_bf16.h>
#include <cuda_fp16.h>
#include <cstdint>

// Problem constants (fixed by setup_inputs)
#define N_NODES 100000
#define NPAD    100096               // 782 * 128 (padded M for GEMM tiles)
#define N_REL   3
#define N_EDGES 1600000
#define DIM     128
#define OUT_DIM 64
#define K_DIM   (N_REL * DIM)        // 384
#define RN      (N_REL * N_NODES)    // 300000
#define TOT_E   (N_REL * N_EDGES)    // 4800000

// ---------------- scratch (device globals; zero-initialized) ----------------
__device__ int   g_deg_out[RN];
__device__ int   g_deg_in[RN];
__device__ float g_inv_out[RN];
__device__ float g_inv_in[RN];
__device__ int   g_row_start[RN];
__device__ int   g_cursor[RN];
__device__ int   g_bsum_scan[1024];
__device__ int2  g_edges[TOT_E];             // {src, bits(inv_out[src])}
__device__ __align__(16) __half g_x16[N_NODES * DIM];   // fp16 input features
__device__ __align__(16) __half g_h16A[N_NODES * DIM];  // fp16 hidden A
__device__ __align__(16) __half g_h16B[N_NODES * DIM];  // fp16 hidden B
__device__ __align__(16) __half g_P16[NPAD * K_DIM];    // aggregated features (fp16)
__device__ __align__(16) __half g_W16[K_DIM * 128];     // W fp16 [384][128] (cols zero-padded)
__device__ float g_bias[128];                           // sum_r b_r, padded

__device__ __forceinline__ uint32_t smem_u32(const void* p) {
    uint32_t a;
    asm("{ .reg .u64 t; cvta.to.shared.u64 t, %1; cvt.u32.u64 %0, t; }" : "=r"(a) : "l"(p));
    return a;
}
#define CP16(dst, src) \
    asm volatile("cp.async.ca.shared.global [%0], [%1], 16;" :: "r"(dst), "l"(src))
#define CP_COMMIT() asm volatile("cp.async.commit_group;" ::: "memory")
#define CP_WAIT1()  asm volatile("cp.async.wait_group 1;" ::: "memory")

// ---------------- CSR build -------------------------------------------------
__global__ void k_zero_deg() {
    int i = blockIdx.x * blockDim.x + threadIdx.x;
    if (i < RN) { g_deg_out[i] = 0; g_deg_in[i] = 0; }
}
__global__ void k_count(const int* __restrict__ src, const int* __restrict__ dst) {
    int i = blockIdx.x * blockDim.x + threadIdx.x;
    if (i < TOT_E) {
        int r = i / N_EDGES;
        atomicAdd(&g_deg_out[r * N_NODES + src[i]], 1);
        atomicAdd(&g_deg_in [r * N_NODES + dst[i]], 1);
    }
}
__global__ void k_scan1() {
    __shared__ int sh[1024];
    int t = threadIdx.x, g = blockIdx.x * 1024 + t;
    int v = (g < RN) ? g_deg_in[g] : 0;
    sh[t] = v; __syncthreads();
    for (int off = 1; off < 1024; off <<= 1) {
        int x = (t >= off) ? sh[t - off] : 0;
        __syncthreads(); sh[t] += x; __syncthreads();
    }
    if (g < RN) g_row_start[g] = sh[t] - v;
    if (t == 1023) g_bsum_scan[blockIdx.x] = sh[t];
}
__global__ void k_scan2(int nblk) {
    __shared__ int sh[1024];
    int t = threadIdx.x;
    int v = (t < nblk) ? g_bsum_scan[t] : 0;
    sh[t] = v; __syncthreads();
    for (int off = 1; off < 1024; off <<= 1) {
        int x = (t >= off) ? sh[t - off] : 0;
        __syncthreads(); sh[t] += x; __syncthreads();
    }
    if (t < nblk) g_bsum_scan[t] = sh[t] - v;
}
// scan finalize + inverse-degree norms (fused)
__global__ void k_scan3() {
    int i = blockIdx.x * blockDim.x + threadIdx.x;
    if (i < RN) {
        int rs = g_row_start[i] + g_bsum_scan[i >> 10];
        g_row_start[i] = rs;
        g_cursor[i]    = rs;
        g_inv_out[i] = rsqrtf((float)max(g_deg_out[i], 1));
        g_inv_in [i] = rsqrtf((float)max(g_deg_in [i], 1));
    }
}
__global__ void k_fill(const int* __restrict__ src, const int* __restrict__ dst) {
    int i = blockIdx.x * blockDim.x + threadIdx.x;
    if (i < TOT_E) {
        int r = i / N_EDGES;
        int s = src[i], d = dst[i];
        int pos = atomicAdd(&g_cursor[r * N_NODES + d], 1);
        g_edges[pos] = make_int2(s, __float_as_int(g_inv_out[r * N_NODES + s]));
    }
}

// ---------------- x -> fp16 (once per call) ----------------------------------
__global__ void k_cvt_x(const float4* __restrict__ x) {
    int i = blockIdx.x * blockDim.x + threadIdx.x;   // one float4 -> 4 halfs
    if (i < N_NODES * DIM / 4) {
        float4 v = x[i];
        uint2 o;
        __half2 p0 = __floats2half2_rn(v.x, v.y);
        __half2 p1 = __floats2half2_rn(v.z, v.w);
        o.x = *(uint32_t*)&p0;
        o.y = *(uint32_t*)&p1;
        ((uint2*)g_x16)[i] = o;
    }
}

// ---------------- aggregation (fp16 gather) -> fp16 P ------------------------
// one warp per (relation, node); warp-uniform edge loads, 4x unroll
__global__ void k_agg(int sel) {
    const uint2* __restrict__ h = (sel == 0) ? (const uint2*)g_x16
                                : (sel == 1) ? (const uint2*)g_h16A
                                             : (const uint2*)g_h16B;
    int wid  = (blockIdx.x * blockDim.x + threadIdx.x) >> 5;
    int lane = threadIdx.x & 31;
    if (wid >= RN) return;
    int start = g_row_start[wid];
    int len   = g_deg_in[wid];
    const int2* __restrict__ ep = g_edges + start;
    float4 acc = make_float4(0.f, 0.f, 0.f, 0.f);
    int k = 0;
    for (; k + 4 <= len; k += 4) {
        int2 e0 = ep[k];
        int2 e1 = ep[k + 1];
        int2 e2 = ep[k + 2];
        int2 e3 = ep[k + 3];
        uint2 v0 = h[e0.x * 32 + lane];
        uint2 v1 = h[e1.x * 32 + lane];
        uint2 v2 = h[e2.x * 32 + lane];
        uint2 v3 = h[e3.x * 32 + lane];
        float w0 = __int_as_float(e0.y);
        float w1 = __int_as_float(e1.y);
        float w2 = __int_as_float(e2.y);
        float w3 = __int_as_float(e3.y);
        float2 a0 = __half22float2(*(__half2*)&v0.x);
        float2 a1 = __half22float2(*(__half2*)&v0.y);
        float2 b0 = __half22float2(*(__half2*)&v1.x);
        float2 b1 = __half22float2(*(__half2*)&v1.y);
        float2 c0 = __half22float2(*(__half2*)&v2.x);
        float2 c1 = __half22float2(*(__half2*)&v2.y);
        float2 d0 = __half22float2(*(__half2*)&v3.x);
        float2 d1 = __half22float2(*(__half2*)&v3.y);
        acc.x = fmaf(w0, a0.x, acc.x); acc.y = fmaf(w0, a0.y, acc.y);
        acc.z = fmaf(w0, a1.x, acc.z); acc.w = fmaf(w0, a1.y, acc.w);
        acc.x = fmaf(w1, b0.x, acc.x); acc.y = fmaf(w1, b0.y, acc.y);
        acc.z = fmaf(w1, b1.x, acc.z); acc.w = fmaf(w1, b1.y, acc.w);
        acc.x = fmaf(w2, c0.x, acc.x); acc.y = fmaf(w2, c0.y, acc.y);
        acc.z = fmaf(w2, c1.x, acc.z); acc.w = fmaf(w2, c1.y, acc.w);
        acc.x = fmaf(w3, d0.x, acc.x); acc.y = fmaf(w3, d0.y, acc.y);
        acc.z = fmaf(w3, d1.x, acc.z); acc.w = fmaf(w3, d1.y, acc.w);
    }
    for (; k < len; k++) {
        int2 e0 = ep[k];
        uint2 v0 = h[e0.x * 32 + lane];
        float w0 = __int_as_float(e0.y);
        float2 a0 = __half22float2(*(__half2*)&v0.x);
        float2 a1 = __half22float2(*(__half2*)&v0.y);
        acc.x = fmaf(w0, a0.x, acc.x); acc.y = fmaf(w0, a0.y, acc.y);
        acc.z = fmaf(w0, a1.x, acc.z); acc.w = fmaf(w0, a1.y, acc.w);
    }
    float si = g_inv_in[wid];
    acc.x *= si; acc.y *= si; acc.z *= si; acc.w *= si;
    int n = wid % N_NODES;
    int r = wid / N_NODES;
    uint2 o;
    __half2 p0 = __floats2half2_rn(acc.x, acc.y);
    __half2 p1 = __floats2half2_rn(acc.z, acc.w);
    o.x = *(uint32_t*)&p0;
    o.y = *(uint32_t*)&p1;
    int idx8 = n * 96 + r * 32 + lane;         // uint2 index into [NPAD][384]
    ((uint2*)g_P16)[idx8] = o;
}

// ---------------- per-layer weight prep: fp16 + combined bias ----------------
__global__ void k_prep(const float* __restrict__ W, const float* __restrict__ b, int ncols) {
    int idx = blockIdx.x * blockDim.x + threadIdx.x;   // idx = k*128 + n
    if (idx < K_DIM * 128) {
        int k = idx >> 7;
        int n = idx & 127;
        float w = (n < ncols) ? W[k * ncols + n] : 0.f;
        g_W16[idx] = __float2half_rn(w);
    }
    if (idx < 128)
        g_bias[idx] = (idx < ncols) ? b[idx] + b[ncols + idx] + b[2 * ncols + idx] : 0.f;
}

// ---------------- HMMA GEMM: C = [relu]( P @ W + bsum ) ----------------------
// 128x128 CTA tile, 8 warps of 32x64, mma.m16n8k16 fp16.
// 12 K-chunks of 32. 3-stage cp.async pipeline.
#define ASTRIDE 40    // 32 + 8 pad (fp16)
#define BSTRIDE 136   // 128 + 8 pad (fp16)
#define ABYTES  (128 * ASTRIDE * 2)        // 10240
#define BBYTES  (32 * BSTRIDE * 2)         // 8704
#define STG     (ABYTES + BBYTES)          // 18944
#define GEMM_SMEM (3 * STG)                // 56832
#define NIT 12

__device__ __forceinline__ void gemm_load_stage(uint32_t sbase, int s, int slot, int row0,
                                                int a_row, int a_col, int b_row, int b_col) {
    int kk = s * 32;
    const __half* ap = g_P16 + (size_t)(row0 + a_row) * K_DIM + kk + a_col;
    const __half* bp = g_W16 + (size_t)(kk + b_row) * 128 + b_col;
    uint32_t da = sbase + slot * STG + (a_row * ASTRIDE + a_col) * 2;
    uint32_t db = sbase + slot * STG + ABYTES + (b_row * BSTRIDE + b_col) * 2;
    CP16(da,      ap);
    CP16(da + 16, ap + 8);
    CP16(db,      bp);
    CP16(db + 16, bp + 8);
}

template <bool RELU>
__global__ void __launch_bounds__(256) k_gemm_mma(float* Cext, int osel, int ncols) {
    extern __shared__ __align__(16) char smem[];
    uint32_t sbase = smem_u32(smem);

    int t = threadIdx.x;
    int w = t >> 5, lane = t & 31;
    int wm = w & 3, wn = w >> 2;
    int row0 = blockIdx.x * 128;

    float d[2][8][4];
#pragma unroll
    for (int i = 0; i < 2; i++)
#pragma unroll
        for (int j = 0; j < 8; j++)
#pragma unroll
            for (int k = 0; k < 4; k++) d[i][j][k] = 0.f;

    int a_row = t >> 1;           // 0..127
    int a_col = (t & 1) * 16;     // 0 or 16
    int b_row = t >> 3;           // 0..31
    int b_col = (t & 7) * 16;     // 0..112

    gemm_load_stage(sbase, 0, 0, row0, a_row, a_col, b_row, b_col); CP_COMMIT();
    gemm_load_stage(sbase, 1, 1, row0, a_row, a_col, b_row, b_col); CP_COMMIT();

    int slot = 0, slot2 = 2;
    for (int it = 0; it < NIT; it++) {
        CP_WAIT1();
        __syncthreads();
        if (it + 2 < NIT)
            gemm_load_stage(sbase, it + 2, slot2, row0, a_row, a_col, b_row, b_col);
        CP_COMMIT();

        uint32_t sA = sbase + slot * STG;
        uint32_t sB = sA + ABYTES;
#pragma unroll
        for (int kh = 0; kh < 32; kh += 16) {
            uint32_t a[2][4];
#pragma unroll
            for (int mi = 0; mi < 2; mi++) {
                uint32_t addr = sA + (uint32_t)(((wm * 32 + mi * 16 + (lane & 15)) * ASTRIDE
                                                 + kh + (lane >> 4) * 8) * 2);
                asm volatile("ldmatrix.sync.aligned.m8n8.x4.shared.b16 {%0,%1,%2,%3}, [%4];"
                    : "=r"(a[mi][0]), "=r"(a[mi][1]), "=r"(a[mi][2]), "=r"(a[mi][3]) : "r"(addr));
            }
            uint32_t bfr[8][2];
#pragma unroll
            for (int nj = 0; nj < 4; nj++) {
                uint32_t addr = sB + (uint32_t)(((kh + (lane & 15)) * BSTRIDE
                                                 + wn * 64 + nj * 16 + (lane >> 4) * 8) * 2);
                uint32_t b0, b1, b2, b3;
                asm volatile("ldmatrix.sync.aligned.m8n8.x4.trans.shared.b16 {%0,%1,%2,%3}, [%4];"
                    : "=r"(b0), "=r"(b1), "=r"(b2), "=r"(b3) : "r"(addr));
                bfr[nj * 2][0] = b0; bfr[nj * 2][1] = b1;
                bfr[nj * 2 + 1][0] = b2; bfr[nj * 2 + 1][1] = b3;
            }
#pragma unroll
            for (int mi = 0; mi < 2; mi++)
#pragma unroll
                for (int nj = 0; nj < 8; nj++)
                    asm volatile("mma.sync.aligned.m16n8k16.row.col.f32.f16.f16.f32 "
                        "{%0,%1,%2,%3}, {%4,%5,%6,%7}, {%8,%9}, {%0,%1,%2,%3};"
                        : "+f"(d[mi][nj][0]), "+f"(d[mi][nj][1]),
                          "+f"(d[mi][nj][2]), "+f"(d[mi][nj][3])
                        : "r"(a[mi][0]), "r"(a[mi][1]), "r"(a[mi][2]), "r"(a[mi][3]),
                          "r"(bfr[nj][0]), "r"(bfr[nj][1]));
        }
        slot  = (slot  == 2) ? 0 : slot + 1;
        slot2 = (slot2 == 2) ? 0 : slot2 + 1;
    }

    // epilogue
    if (wn * 64 >= ncols) return;
    __half* outh = (osel == 1) ? g_h16A : g_h16B;
    int cbase = wn * 64 + (lane & 3) * 2;
#pragma unroll
    for (int mi = 0; mi < 2; mi++) {
#pragma unroll
        for (int half_ = 0; half_ < 2; half_++) {
            int row = row0 + wm * 32 + mi * 16 + (lane >> 2) + half_ * 8;
            if (row >= N_NODES) continue;
#pragma unroll
            for (int nj = 0; nj < 8; nj++) {
                int c = cbase + nj * 8;
                float v0 = d[mi][nj][half_ * 2 + 0] + g_bias[c];
                float v1 = d[mi][nj][half_ * 2 + 1] + g_bias[c + 1];
                if (RELU) {
                    v0 = fmaxf(v0, 0.f); v1 = fmaxf(v1, 0.f);
                    *(__half2*)(outh + (size_t)row * DIM + c) = __floats2half2_rn(v0, v1);
                } else {
                    *(float2*)(Cext + (size_t)row * ncols + c) = make_float2(v0, v1);
                }
            }
        }
    }
}

// ---------------- launch ----------------------------------------------------
extern "C" void kernel_launch(void* const* d_in, const int* in_sizes, int n_in,
                              void* d_out, int out_size) {
    const float* x   = (const float*)d_in[0];
    const int*   src = (const int*)d_in[1];
    const int*   dst = (const int*)d_in[2];
    const float* W[6];
    const float* b[6];
    for (int l = 0; l < 6; l++) {
        W[l] = (const float*)d_in[3 + 2 * l];
        b[l] = (const float*)d_in[4 + 2 * l];
    }

    cudaFuncSetAttribute(k_gemm_mma<true>,  cudaFuncAttributeMaxDynamicSharedMemorySize, GEMM_SMEM);
    cudaFuncSetAttribute(k_gemm_mma<false>, cudaFuncAttributeMaxDynamicSharedMemorySize, GEMM_SMEM);

    const int T = 256;
    k_zero_deg<<<(RN + T - 1) / T, T>>>();
    k_count<<<(TOT_E + T - 1) / T, T>>>(src, dst);
    int nblk = (RN + 1023) / 1024;
    k_scan1<<<nblk, 1024>>>();
    k_scan2<<<1, 1024>>>(nblk);
    k_scan3<<<(RN + T - 1) / T, T>>>();
    k_fill<<<(TOT_E + T - 1) / T, T>>>(src, dst);
    k_cvt_x<<<(N_NODES * DIM / 4 + T - 1) / T, T>>>((const float4*)x);

    int agg_blocks  = (RN * 32 + T - 1) / T;
    int gemm_blocks = NPAD / 128;   // 782

    int in_sel [6] = {0, 1, 2, 1, 2, 1};
    int out_sel[6] = {1, 2, 1, 2, 1, 0};

    for (int l = 0; l < 6; l++) {
        int ncols = (l == 5) ? OUT_DIM : DIM;
        k_prep<<<(K_DIM * 128 + T - 1) / T, T>>>(W[l], b[l], ncols);
        k_agg<<<agg_blocks, T>>>(in_sel[l]);
        if (l == 5)
            k_gemm_mma<false><<<gemm_blocks, T, GEMM_SMEM>>>((float*)d_out, 0, ncols);
        else
            k_gemm_mma<true><<<gemm_blocks, T, GEMM_SMEM>>>(nullptr, out_sel[l], ncols);
    }
}